// round 1
// baseline (speedup 1.0000x reference)
#include <cuda_runtime.h>
#include <math.h>

// Problem constants
#define NTOK 2048
#define HDIM 2048
#define IDIM 1408
#define NEXP 8
#define ISH  2816
#define TOPK 2
#define CAP  5120   // 4096 rows + worst-case 127 pad per expert, rounded up

// ----------------------------- scratch (device globals, no runtime alloc) ---
__device__ int   g_cnt[NEXP];
__device__ int   g_cnt2[NEXP];
__device__ int   g_off[NEXP];
__device__ int   g_rows_token[CAP];
__device__ int   g_rows_slot[CAP];
__device__ float g_rows_w[CAP];
__device__ int   g_tki[NTOK * TOPK];
__device__ float g_tkw[NTOK * TOPK];
__device__ float g_hbuf[(size_t)CAP * IDIM];            // routed SwiGLU activations
__device__ float g_partial[(size_t)NTOK * TOPK * HDIM]; // routed down-proj, per (n,k)
__device__ float g_sbuf[(size_t)NTOK * ISH];            // shared-expert SwiGLU activations

// ----------------------------- reset ----------------------------------------
__global__ void k_reset() {
    int i = blockIdx.x * blockDim.x + threadIdx.x;
    if (i < NEXP) { g_cnt[i] = 0; g_cnt2[i] = 0; }
    if (i < CAP)  { g_rows_token[i] = -1; g_rows_slot[i] = -1; g_rows_w[i] = 0.f; }
}

// ----------------------------- gate: logits -> softmax -> top2 --------------
__global__ void k_gate(const float* __restrict__ x, const float* __restrict__ gw) {
    int n = blockIdx.x;
    int tid = threadIdx.x;
    const float* xr = x + (size_t)n * HDIM;
    float acc[NEXP];
#pragma unroll
    for (int e = 0; e < NEXP; e++) acc[e] = 0.f;
    for (int h = tid; h < HDIM; h += 128) {
        float xv = xr[h];
#pragma unroll
        for (int e = 0; e < NEXP; e++) acc[e] += xv * gw[e * HDIM + h];
    }
    __shared__ float s[NEXP][128];
#pragma unroll
    for (int e = 0; e < NEXP; e++) s[e][tid] = acc[e];
    __syncthreads();
    for (int st = 64; st > 0; st >>= 1) {
        if (tid < st) {
#pragma unroll
            for (int e = 0; e < NEXP; e++) s[e][tid] += s[e][tid + st];
        }
        __syncthreads();
    }
    if (tid == 0) {
        float l[NEXP];
        float m = -1e30f;
#pragma unroll
        for (int e = 0; e < NEXP; e++) { l[e] = s[e][0]; m = fmaxf(m, l[e]); }
        float d = 0.f;
#pragma unroll
        for (int e = 0; e < NEXP; e++) d += expf(l[e] - m);
        int i1 = 0;
#pragma unroll
        for (int e = 1; e < NEXP; e++) if (l[e] > l[i1]) i1 = e;
        int i2 = -1;
#pragma unroll
        for (int e = 0; e < NEXP; e++) {
            if (e == i1) continue;
            if (i2 < 0 || l[e] > l[i2]) i2 = e;
        }
        float w1 = expf(l[i1] - m) / d;
        float w2 = expf(l[i2] - m) / d;
        g_tki[n * 2 + 0] = i1; g_tkw[n * 2 + 0] = w1;
        g_tki[n * 2 + 1] = i2; g_tkw[n * 2 + 1] = w2;
    }
}

// ----------------------------- binning --------------------------------------
__global__ void k_count() {
    int i = blockIdx.x * blockDim.x + threadIdx.x;
    if (i < NTOK * TOPK) atomicAdd(&g_cnt[g_tki[i]], 1);
}
__global__ void k_scan() {
    if (threadIdx.x == 0 && blockIdx.x == 0) {
        int o = 0;
        for (int e = 0; e < NEXP; e++) {
            g_off[e] = o;
            o += ((g_cnt[e] + 127) / 128) * 128;
        }
    }
}
__global__ void k_place() {
    int i = blockIdx.x * blockDim.x + threadIdx.x;
    if (i < NTOK * TOPK) {
        int e = g_tki[i];
        int p = g_off[e] + atomicAdd(&g_cnt2[e], 1);
        g_rows_token[p] = i >> 1;
        g_rows_slot[p]  = i;          // n*2 + k
        g_rows_w[p]     = g_tkw[i];
    }
}

// ----------------------------- dual-B SwiGLU GEMM ----------------------------
// C[row, :] = silu(A[row,:] @ B1) * (A[row,:] @ B2)
// ROUTED: A rows gathered via g_rows_token, per-expert B slice, C = g_hbuf.
// !ROUTED: identity rows, C = g_sbuf.
template<bool ROUTED, int NCOLS, int K>
__global__ void __launch_bounds__(256, 2) k_swiglu(
    const float* __restrict__ X,
    const float* __restrict__ B1g,
    const float* __restrict__ B2g)
{
    const int e = blockIdx.z;
    int cnt, rowbase;
    if (ROUTED) { cnt = g_cnt[e]; rowbase = g_off[e]; }
    else        { cnt = NTOK;     rowbase = 0; }
    const int m0 = blockIdx.x * 128;
    if (m0 >= cnt) return;
    const int n0 = blockIdx.y * 64;
    const float* B1 = B1g + (ROUTED ? (size_t)e * K * NCOLS : 0);
    const float* B2 = B2g + (ROUTED ? (size_t)e * K * NCOLS : 0);
    float* C = ROUTED ? g_hbuf : g_sbuf;

    __shared__ float As[16][128];
    __shared__ float Bs1[16][64];
    __shared__ float Bs2[16][64];

    const int tid = threadIdx.x;
    const int tm = tid >> 4, tn = tid & 15;

    // Resolve gathered A pointers for the 2 float4 load slots of this thread.
    const float* aptr[2];
#pragma unroll
    for (int i = 0; i < 2; i++) {
        int idx = i * 256 + tid;
        int r = idx >> 2, kq = idx & 3;
        int gr = m0 + r;
        int tok;
        if (ROUTED) tok = (gr < cnt) ? g_rows_token[rowbase + gr] : -1;
        else        tok = gr;
        aptr[i] = (tok >= 0) ? (X + (size_t)tok * K + kq * 4) : (const float*)0;
    }
    const int bk = tid >> 4;
    const int bn = (tid & 15) * 4;

    float acc1[8][4], acc2[8][4];
#pragma unroll
    for (int i = 0; i < 8; i++)
#pragma unroll
        for (int j = 0; j < 4; j++) { acc1[i][j] = 0.f; acc2[i][j] = 0.f; }

    for (int k0 = 0; k0 < K; k0 += 16) {
#pragma unroll
        for (int i = 0; i < 2; i++) {
            int idx = i * 256 + tid;
            int r = idx >> 2, kq = idx & 3;
            float4 v = make_float4(0.f, 0.f, 0.f, 0.f);
            if (aptr[i]) v = *(const float4*)(aptr[i] + k0);
            As[kq * 4 + 0][r] = v.x; As[kq * 4 + 1][r] = v.y;
            As[kq * 4 + 2][r] = v.z; As[kq * 4 + 3][r] = v.w;
        }
        {
            float4 v1 = *(const float4*)(B1 + (size_t)(k0 + bk) * NCOLS + n0 + bn);
            float4 v2 = *(const float4*)(B2 + (size_t)(k0 + bk) * NCOLS + n0 + bn);
            *(float4*)&Bs1[bk][bn] = v1;
            *(float4*)&Bs2[bk][bn] = v2;
        }
        __syncthreads();
#pragma unroll
        for (int kk = 0; kk < 16; kk++) {
            float a[8], b1f[4], b2f[4];
            *(float4*)&a[0] = *(const float4*)&As[kk][tm * 8];
            *(float4*)&a[4] = *(const float4*)&As[kk][tm * 8 + 4];
            *(float4*)&b1f[0] = *(const float4*)&Bs1[kk][tn * 4];
            *(float4*)&b2f[0] = *(const float4*)&Bs2[kk][tn * 4];
#pragma unroll
            for (int ii = 0; ii < 8; ii++)
#pragma unroll
                for (int jj = 0; jj < 4; jj++) {
                    acc1[ii][jj] += a[ii] * b1f[jj];
                    acc2[ii][jj] += a[ii] * b2f[jj];
                }
        }
        __syncthreads();
    }

#pragma unroll
    for (int ii = 0; ii < 8; ii++) {
        int gr = m0 + tm * 8 + ii;
        size_t crow = (size_t)(rowbase + gr);
        float4 o;
        float c1, c2;
        c1 = acc1[ii][0]; c2 = acc2[ii][0]; o.x = c1 / (1.f + expf(-c1)) * c2;
        c1 = acc1[ii][1]; c2 = acc2[ii][1]; o.y = c1 / (1.f + expf(-c1)) * c2;
        c1 = acc1[ii][2]; c2 = acc2[ii][2]; o.z = c1 / (1.f + expf(-c1)) * c2;
        c1 = acc1[ii][3]; c2 = acc2[ii][3]; o.w = c1 / (1.f + expf(-c1)) * c2;
        *(float4*)(C + crow * NCOLS + n0 + tn * 4) = o;
    }
}

// ----------------------------- down-proj GEMM --------------------------------
// ROUTED: A = g_hbuf (contiguous per-expert rows), B = w_down[e],
//         scatter rows * routing weight into g_partial[slot].
// !ROUTED: A = g_sbuf, B = sw_down, write straight into d_out.
template<bool ROUTED, int NCOLS, int K>
__global__ void __launch_bounds__(256, 2) k_down(
    const float* __restrict__ Bg,
    float* __restrict__ Cout)
{
    const int e = blockIdx.z;
    int cnt, rowbase;
    if (ROUTED) { cnt = g_cnt[e]; rowbase = g_off[e]; }
    else        { cnt = NTOK;     rowbase = 0; }
    const int m0 = blockIdx.x * 128;
    if (m0 >= cnt) return;
    const int n0 = blockIdx.y * 128;
    const float* B = Bg + (ROUTED ? (size_t)e * K * NCOLS : 0);
    const float* A = ROUTED ? g_hbuf : g_sbuf;

    __shared__ float As[16][128];
    __shared__ float Bs[16][128];

    const int tid = threadIdx.x;
    const int tm = tid >> 4, tn = tid & 15;

    float acc[8][8];
#pragma unroll
    for (int i = 0; i < 8; i++)
#pragma unroll
        for (int j = 0; j < 8; j++) acc[i][j] = 0.f;

    for (int k0 = 0; k0 < K; k0 += 16) {
#pragma unroll
        for (int i = 0; i < 2; i++) {
            int idx = i * 256 + tid;
            int r = idx >> 2, kq = idx & 3;
            float4 v = *(const float4*)(A + (size_t)(rowbase + m0 + r) * K + k0 + kq * 4);
            As[kq * 4 + 0][r] = v.x; As[kq * 4 + 1][r] = v.y;
            As[kq * 4 + 2][r] = v.z; As[kq * 4 + 3][r] = v.w;
        }
#pragma unroll
        for (int i = 0; i < 2; i++) {
            int idx = i * 256 + tid;
            int k = idx >> 5, nq = (idx & 31) * 4;
            float4 v = *(const float4*)(B + (size_t)(k0 + k) * NCOLS + n0 + nq);
            *(float4*)&Bs[k][nq] = v;
        }
        __syncthreads();
#pragma unroll
        for (int kk = 0; kk < 16; kk++) {
            float a[8], b[8];
            *(float4*)&a[0] = *(const float4*)&As[kk][tm * 8];
            *(float4*)&a[4] = *(const float4*)&As[kk][tm * 8 + 4];
            *(float4*)&b[0] = *(const float4*)&Bs[kk][tn * 8];
            *(float4*)&b[4] = *(const float4*)&Bs[kk][tn * 8 + 4];
#pragma unroll
            for (int ii = 0; ii < 8; ii++)
#pragma unroll
                for (int jj = 0; jj < 8; jj++) acc[ii][jj] += a[ii] * b[jj];
        }
        __syncthreads();
    }

    if (ROUTED) {
#pragma unroll
        for (int ii = 0; ii < 8; ii++) {
            int grow = rowbase + m0 + tm * 8 + ii;
            int slot = g_rows_slot[grow];
            if (slot >= 0) {
                float w = g_rows_w[grow];
                float* p = g_partial + (size_t)slot * HDIM + n0 + tn * 8;
                float4 o0, o1;
                o0.x = w * acc[ii][0]; o0.y = w * acc[ii][1];
                o0.z = w * acc[ii][2]; o0.w = w * acc[ii][3];
                o1.x = w * acc[ii][4]; o1.y = w * acc[ii][5];
                o1.z = w * acc[ii][6]; o1.w = w * acc[ii][7];
                *(float4*)p = o0;
                *(float4*)(p + 4) = o1;
            }
        }
    } else {
#pragma unroll
        for (int ii = 0; ii < 8; ii++) {
            int row = m0 + tm * 8 + ii;
            float* p = Cout + (size_t)row * NCOLS + n0 + tn * 8;
            float4 o0, o1;
            o0.x = acc[ii][0]; o0.y = acc[ii][1]; o0.z = acc[ii][2]; o0.w = acc[ii][3];
            o1.x = acc[ii][4]; o1.y = acc[ii][5]; o1.z = acc[ii][6]; o1.w = acc[ii][7];
            *(float4*)p = o0;
            *(float4*)(p + 4) = o1;
        }
    }
}

// ----------------------------- final combine ---------------------------------
__global__ void k_combine(float* __restrict__ out) {
    size_t base = ((size_t)blockIdx.x * blockDim.x + threadIdx.x) * 4;
    if (base >= (size_t)NTOK * HDIM) return;
    int n = (int)(base >> 11);          // HDIM = 2048
    int h = (int)(base & 2047);
    float4 o  = *(float4*)(out + base);
    float4 p0 = *(float4*)&g_partial[(size_t)(2 * n) * HDIM + h];
    float4 p1 = *(float4*)&g_partial[(size_t)(2 * n + 1) * HDIM + h];
    o.x += p0.x + p1.x;
    o.y += p0.y + p1.y;
    o.z += p0.z + p1.z;
    o.w += p0.w + p1.w;
    *(float4*)(out + base) = o;
}

// ----------------------------- launch ----------------------------------------
extern "C" void kernel_launch(void* const* d_in, const int* in_sizes, int n_in,
                              void* d_out, int out_size)
{
    const float* x       = (const float*)d_in[0];
    const float* gate_w  = (const float*)d_in[1];
    const float* w_gate  = (const float*)d_in[2];
    const float* w_up    = (const float*)d_in[3];
    const float* w_down  = (const float*)d_in[4];
    const float* sw_gate = (const float*)d_in[5];
    const float* sw_up   = (const float*)d_in[6];
    const float* sw_down = (const float*)d_in[7];
    float* out = (float*)d_out;

    k_reset<<<(CAP + 255) / 256, 256>>>();
    k_gate<<<NTOK, 128>>>(x, gate_w);
    k_count<<<(NTOK * TOPK + 255) / 256, 256>>>();
    k_scan<<<1, 32>>>();
    k_place<<<(NTOK * TOPK + 255) / 256, 256>>>();

    // routed SwiGLU: per-expert tiles over M (up to 2048 rows) x I
    {
        dim3 grid(NTOK / 128, IDIM / 64, NEXP);
        k_swiglu<true, IDIM, HDIM><<<grid, 256>>>(x, w_gate, w_up);
    }
    // shared SwiGLU: 2048 x ISH
    {
        dim3 grid(NTOK / 128, ISH / 64, 1);
        k_swiglu<false, ISH, HDIM><<<grid, 256>>>(x, sw_gate, sw_up);
    }
    // routed down-proj -> g_partial (weighted scatter)
    {
        dim3 grid(NTOK / 128, HDIM / 128, NEXP);
        k_down<true, HDIM, IDIM><<<grid, 256>>>(w_down, out);
    }
    // shared down-proj -> out (initializes every element)
    {
        dim3 grid(NTOK / 128, HDIM / 128, 1);
        k_down<false, HDIM, ISH><<<grid, 256>>>(sw_down, out);
    }
    // out += partial[n,0] + partial[n,1]
    k_combine<<<(NTOK * HDIM / 4 + 255) / 256, 256>>>(out);
}

// round 3
// speedup vs baseline: 1.7244x; 1.7244x over previous
#include <cuda_runtime.h>
#include <math.h>
#include <stdint.h>

// Problem constants
#define NTOK 2048
#define HDIM 2048
#define IDIM 1408
#define NEXP 8
#define ISH  2816
#define TOPK 2
#define CAP  5120

// ----------------------------- scratch --------------------------------------
__device__ int   g_cnt[NEXP];
__device__ int   g_cnt2[NEXP];
__device__ int   g_off[NEXP];
__device__ int   g_rows_token[CAP];
__device__ int   g_rows_slot[CAP];
__device__ float g_rows_w[CAP];
__device__ int   g_tki[NTOK * TOPK];
__device__ float g_tkw[NTOK * TOPK];
__device__ float g_hbuf[(size_t)CAP * IDIM];
__device__ float g_partial[(size_t)NTOK * TOPK * HDIM];
__device__ float g_sbuf[(size_t)NTOK * ISH];

// ----------------------------- helpers --------------------------------------
__device__ __forceinline__ float tf32r(float x) {
    uint32_t r;
    asm("cvt.rna.tf32.f32 %0, %1;" : "=r"(r) : "f"(x));
    return __uint_as_float(r);
}
// k-position within a 32-k chunk row: pairs (k, k+4) adjacent -> LDS.64 frags
#define POS(k) (((k) & 24) + (((k) & 3) << 1) + (((k) >> 2) & 1))

#define MMA8(c, a, b0, b1) \
    asm volatile("mma.sync.aligned.m16n8k8.row.col.f32.tf32.tf32.f32 " \
        "{%0,%1,%2,%3},{%4,%5,%6,%7},{%8,%9},{%0,%1,%2,%3};" \
        : "+f"((c)[0]), "+f"((c)[1]), "+f"((c)[2]), "+f"((c)[3]) \
        : "r"((a)[0]), "r"((a)[1]), "r"((a)[2]), "r"((a)[3]), "r"(b0), "r"(b1))

// SMEM stage layout (floats): A[0,5120) = 128 rows x 40, then B region 5120 floats
#define STG_FLOATS 10240
#define SMEMSZ_MMA (2 * STG_FLOATS * 4)

// ----------------------------- small kernels ---------------------------------
__global__ void k_reset() {
    int i = blockIdx.x * blockDim.x + threadIdx.x;
    if (i < NEXP) { g_cnt[i] = 0; g_cnt2[i] = 0; }
    if (i < CAP)  { g_rows_token[i] = -1; g_rows_slot[i] = -1; g_rows_w[i] = 0.f; }
}

__global__ void k_gate(const float* __restrict__ x, const float* __restrict__ gw) {
    int n = blockIdx.x;
    int tid = threadIdx.x;
    const float* xr = x + (size_t)n * HDIM;
    float acc[NEXP];
#pragma unroll
    for (int e = 0; e < NEXP; e++) acc[e] = 0.f;
    for (int h = tid; h < HDIM; h += 128) {
        float xv = xr[h];
#pragma unroll
        for (int e = 0; e < NEXP; e++) acc[e] += xv * gw[e * HDIM + h];
    }
    __shared__ float s[NEXP][128];
#pragma unroll
    for (int e = 0; e < NEXP; e++) s[e][tid] = acc[e];
    __syncthreads();
    for (int st = 64; st > 0; st >>= 1) {
        if (tid < st) {
#pragma unroll
            for (int e = 0; e < NEXP; e++) s[e][tid] += s[e][tid + st];
        }
        __syncthreads();
    }
    if (tid == 0) {
        float l[NEXP];
        float m = -1e30f;
#pragma unroll
        for (int e = 0; e < NEXP; e++) { l[e] = s[e][0]; m = fmaxf(m, l[e]); }
        float d = 0.f;
#pragma unroll
        for (int e = 0; e < NEXP; e++) d += expf(l[e] - m);
        int i1 = 0;
#pragma unroll
        for (int e = 1; e < NEXP; e++) if (l[e] > l[i1]) i1 = e;
        int i2 = -1;
#pragma unroll
        for (int e = 0; e < NEXP; e++) {
            if (e == i1) continue;
            if (i2 < 0 || l[e] > l[i2]) i2 = e;
        }
        g_tki[n * 2 + 0] = i1; g_tkw[n * 2 + 0] = expf(l[i1] - m) / d;
        g_tki[n * 2 + 1] = i2; g_tkw[n * 2 + 1] = expf(l[i2] - m) / d;
    }
}

__global__ void k_count() {
    int i = blockIdx.x * blockDim.x + threadIdx.x;
    if (i < NTOK * TOPK) atomicAdd(&g_cnt[g_tki[i]], 1);
}
__global__ void k_scan() {
    if (threadIdx.x == 0 && blockIdx.x == 0) {
        int o = 0;
        for (int e = 0; e < NEXP; e++) {
            g_off[e] = o;
            o += ((g_cnt[e] + 127) / 128) * 128;
        }
    }
}
__global__ void k_place() {
    int i = blockIdx.x * blockDim.x + threadIdx.x;
    if (i < NTOK * TOPK) {
        int e = g_tki[i];
        int p = g_off[e] + atomicAdd(&g_cnt2[e], 1);
        g_rows_token[p] = i >> 1;
        g_rows_slot[p]  = i;
        g_rows_w[p]     = g_tkw[i];
    }
}

// ----------------------------- SwiGLU mma GEMM -------------------------------
// CTA tile: 128 M x 64 N, computed against TWO B matrices (gate, up).
// Warps 2x4: warp tile 64 M x 16 N (per matrix). k-chunk 32, double buffered.
template<bool ROUTED, int NCOLS, int K>
__global__ void __launch_bounds__(256) k_swiglu_mma(
    const float* __restrict__ X,
    const float* __restrict__ B1g,
    const float* __restrict__ B2g)
{
    const int e = blockIdx.z;
    const int cnt = ROUTED ? g_cnt[e] : NTOK;
    const int rowbase = ROUTED ? g_off[e] : 0;
    const int m0 = blockIdx.x * 128;
    if (m0 >= cnt) return;
    const int n0 = blockIdx.y * 64;
    const float* B1 = B1g + (ROUTED ? (size_t)e * K * NCOLS : 0);
    const float* B2 = B2g + (ROUTED ? (size_t)e * K * NCOLS : 0);
    float* C = ROUTED ? g_hbuf : g_sbuf;

    extern __shared__ float sm[];
    const int tid = threadIdx.x;
    const int wid = tid >> 5, lane = tid & 31, gid = lane >> 2, tig = lane & 3;
    const int wm = wid >> 2, wn = wid & 3;

    // ---- loader setup ----
    const float* aptr[4];
    int aposb[4];
#pragma unroll
    for (int i = 0; i < 4; i++) {
        int idx = i * 256 + tid;
        int m = idx >> 3, kq = (idx & 7) * 4;
        aposb[i] = m * 40 + (kq & 24) + ((kq >> 2) & 1);
        int tok;
        if (ROUTED) { int gr = m0 + m; tok = (gr < cnt) ? g_rows_token[rowbase + gr] : -1; }
        else tok = m0 + m;
        aptr[i] = (tok >= 0) ? (X + (size_t)tok * K + kq) : (const float*)0;
    }
    const int bk = tid >> 3;
    const int bposk = POS(bk);
    const int bn = (tid & 7) * 8;
    const float* b1p = B1 + (size_t)bk * NCOLS + n0 + bn;
    const float* b2p = B2 + (size_t)bk * NCOLS + n0 + bn;

    float4 ra[4], rb1[2], rb2[2];
    float cg[4][2][4], cu[4][2][4];
#pragma unroll
    for (int mt = 0; mt < 4; mt++)
#pragma unroll
        for (int j = 0; j < 2; j++)
#pragma unroll
            for (int c = 0; c < 4; c++) { cg[mt][j][c] = 0.f; cu[mt][j][c] = 0.f; }

    auto LOAD = [&](int ch) {
        int k0 = ch * 32;
#pragma unroll
        for (int i = 0; i < 4; i++)
            ra[i] = aptr[i] ? *(const float4*)(aptr[i] + k0)
                            : make_float4(0.f, 0.f, 0.f, 0.f);
        size_t bo = (size_t)k0 * NCOLS;
        rb1[0] = *(const float4*)(b1p + bo);
        rb1[1] = *(const float4*)(b1p + bo + 4);
        rb2[0] = *(const float4*)(b2p + bo);
        rb2[1] = *(const float4*)(b2p + bo + 4);
    };
    auto STORE = [&](int buf) {
        float* S = sm + buf * STG_FLOATS;
#pragma unroll
        for (int i = 0; i < 4; i++) {
            float4 v = ra[i];
            float* p = S + aposb[i];
            p[0] = tf32r(v.x); p[2] = tf32r(v.y); p[4] = tf32r(v.z); p[6] = tf32r(v.w);
        }
        float* P1 = S + 5120;
        float* P2 = S + 7680;
        const float* v1 = (const float*)rb1;
        const float* v2 = (const float*)rb2;
#pragma unroll
        for (int c = 0; c < 4; c++) {
            P1[(bn + c) * 40 + bposk]     = tf32r(v1[c]);
            P1[(bn + 4 + c) * 40 + bposk] = tf32r(v1[4 + c]);
            P2[(bn + c) * 40 + bposk]     = tf32r(v2[c]);
            P2[(bn + 4 + c) * 40 + bposk] = tf32r(v2[4 + c]);
        }
    };
    auto COMPUTE = [&](int buf) {
        const float* S = sm + buf * STG_FLOATS;
        const float* P1 = S + 5120;
        const float* P2 = S + 7680;
#pragma unroll
        for (int s = 0; s < 4; s++) {
            uint32_t a[4][4];
#pragma unroll
            for (int mt = 0; mt < 4; mt++) {
                int m = wm * 64 + mt * 16 + gid;
                float2 x02 = *(const float2*)(S + m * 40 + s * 8 + 2 * tig);
                float2 x13 = *(const float2*)(S + (m + 8) * 40 + s * 8 + 2 * tig);
                a[mt][0] = __float_as_uint(x02.x);
                a[mt][1] = __float_as_uint(x13.x);
                a[mt][2] = __float_as_uint(x02.y);
                a[mt][3] = __float_as_uint(x13.y);
            }
#pragma unroll
            for (int j = 0; j < 2; j++) {
                int n = wn * 16 + j * 8 + gid;
                float2 bg = *(const float2*)(P1 + n * 40 + s * 8 + 2 * tig);
                float2 bu = *(const float2*)(P2 + n * 40 + s * 8 + 2 * tig);
                uint32_t g0 = __float_as_uint(bg.x), g1 = __float_as_uint(bg.y);
                uint32_t u0 = __float_as_uint(bu.x), u1 = __float_as_uint(bu.y);
#pragma unroll
                for (int mt = 0; mt < 4; mt++) {
                    MMA8(cg[mt][j], a[mt], g0, g1);
                    MMA8(cu[mt][j], a[mt], u0, u1);
                }
            }
        }
    };

    LOAD(0);
    constexpr int NC = K / 32;
    for (int ch = 0; ch < NC; ch++) {
        STORE(ch & 1);
        __syncthreads();
        if (ch + 1 < NC) LOAD(ch + 1);
        COMPUTE(ch & 1);
    }

    // ---- epilogue: silu(gate)*up ----
#pragma unroll
    for (int mt = 0; mt < 4; mt++) {
        int r0 = m0 + wm * 64 + mt * 16 + gid;
        size_t row0 = (size_t)(rowbase + r0);
        size_t row1 = row0 + 8;
#pragma unroll
        for (int j = 0; j < 2; j++) {
            int col = n0 + wn * 16 + j * 8 + 2 * tig;
            float g0 = cg[mt][j][0], g1 = cg[mt][j][1], g2 = cg[mt][j][2], g3 = cg[mt][j][3];
            float o0 = g0 / (1.f + expf(-g0)) * cu[mt][j][0];
            float o1 = g1 / (1.f + expf(-g1)) * cu[mt][j][1];
            float o2 = g2 / (1.f + expf(-g2)) * cu[mt][j][2];
            float o3 = g3 / (1.f + expf(-g3)) * cu[mt][j][3];
            *(float2*)(C + row0 * NCOLS + col) = make_float2(o0, o1);
            *(float2*)(C + row1 * NCOLS + col) = make_float2(o2, o3);
        }
    }
}

// ----------------------------- down-proj mma GEMM -----------------------------
// CTA tile 128 M x 128 N, warp tile 64 x 32. k-chunk 32, double buffered.
template<bool ROUTED, int NCOLS, int K>
__global__ void __launch_bounds__(256) k_down_mma(
    const float* __restrict__ Bg,
    float* __restrict__ Cout)
{
    const int e = blockIdx.z;
    const int cnt = ROUTED ? g_cnt[e] : NTOK;
    const int rowbase = ROUTED ? g_off[e] : 0;
    const int m0 = blockIdx.x * 128;
    if (m0 >= cnt) return;
    const int n0 = blockIdx.y * 128;
    const float* B = Bg + (ROUTED ? (size_t)e * K * NCOLS : 0);
    const float* A = ROUTED ? g_hbuf : g_sbuf;

    extern __shared__ float sm[];
    const int tid = threadIdx.x;
    const int wid = tid >> 5, lane = tid & 31, gid = lane >> 2, tig = lane & 3;
    const int wm = wid >> 2, wn = wid & 3;

    const float* aptr[4];
    int aposb[4];
#pragma unroll
    for (int i = 0; i < 4; i++) {
        int idx = i * 256 + tid;
        int m = idx >> 3, kq = (idx & 7) * 4;
        aposb[i] = m * 40 + (kq & 24) + ((kq >> 2) & 1);
        aptr[i] = A + (size_t)(rowbase + m0 + m) * K + kq;
    }
    const int bk = tid >> 3;
    const int bposk = POS(bk);
    const int bn = (tid & 7) * 16;
    const float* bp = B + (size_t)bk * NCOLS + n0 + bn;

    float4 ra[4], rb[4];
    float cc[4][4][4];
#pragma unroll
    for (int mt = 0; mt < 4; mt++)
#pragma unroll
        for (int j = 0; j < 4; j++)
#pragma unroll
            for (int c = 0; c < 4; c++) cc[mt][j][c] = 0.f;

    auto LOAD = [&](int ch) {
        int k0 = ch * 32;
#pragma unroll
        for (int i = 0; i < 4; i++)
            ra[i] = *(const float4*)(aptr[i] + k0);
        size_t bo = (size_t)k0 * NCOLS;
#pragma unroll
        for (int i = 0; i < 4; i++)
            rb[i] = *(const float4*)(bp + bo + i * 4);
    };
    auto STORE = [&](int buf) {
        float* S = sm + buf * STG_FLOATS;
#pragma unroll
        for (int i = 0; i < 4; i++) {
            float4 v = ra[i];
            float* p = S + aposb[i];
            p[0] = tf32r(v.x); p[2] = tf32r(v.y); p[4] = tf32r(v.z); p[6] = tf32r(v.w);
        }
        float* P = S + 5120;
        const float* v = (const float*)rb;
#pragma unroll
        for (int i = 0; i < 4; i++)
#pragma unroll
            for (int c = 0; c < 4; c++)
                P[(bn + i * 4 + c) * 40 + bposk] = tf32r(v[i * 4 + c]);
    };
    auto COMPUTE = [&](int buf) {
        const float* S = sm + buf * STG_FLOATS;
        const float* P = S + 5120;
#pragma unroll
        for (int s = 0; s < 4; s++) {
            uint32_t a[4][4];
#pragma unroll
            for (int mt = 0; mt < 4; mt++) {
                int m = wm * 64 + mt * 16 + gid;
                float2 x02 = *(const float2*)(S + m * 40 + s * 8 + 2 * tig);
                float2 x13 = *(const float2*)(S + (m + 8) * 40 + s * 8 + 2 * tig);
                a[mt][0] = __float_as_uint(x02.x);
                a[mt][1] = __float_as_uint(x13.x);
                a[mt][2] = __float_as_uint(x02.y);
                a[mt][3] = __float_as_uint(x13.y);
            }
#pragma unroll
            for (int j = 0; j < 4; j++) {
                int n = wn * 32 + j * 8 + gid;
                float2 b01 = *(const float2*)(P + n * 40 + s * 8 + 2 * tig);
                uint32_t b0 = __float_as_uint(b01.x), b1 = __float_as_uint(b01.y);
#pragma unroll
                for (int mt = 0; mt < 4; mt++)
                    MMA8(cc[mt][j], a[mt], b0, b1);
            }
        }
    };

    LOAD(0);
    constexpr int NC = K / 32;
    for (int ch = 0; ch < NC; ch++) {
        STORE(ch & 1);
        __syncthreads();
        if (ch + 1 < NC) LOAD(ch + 1);
        COMPUTE(ch & 1);
    }

    // ---- epilogue ----
#pragma unroll
    for (int mt = 0; mt < 4; mt++) {
        int r0 = m0 + wm * 64 + mt * 16 + gid;
        int gr0 = rowbase + r0, gr1 = gr0 + 8;
        if (ROUTED) {
            int s0 = g_rows_slot[gr0], s1 = g_rows_slot[gr1];
            float w0 = g_rows_w[gr0],  w1 = g_rows_w[gr1];
#pragma unroll
            for (int j = 0; j < 4; j++) {
                int col = n0 + wn * 32 + j * 8 + 2 * tig;
                if (s0 >= 0)
                    *(float2*)(g_partial + (size_t)s0 * HDIM + col) =
                        make_float2(w0 * cc[mt][j][0], w0 * cc[mt][j][1]);
                if (s1 >= 0)
                    *(float2*)(g_partial + (size_t)s1 * HDIM + col) =
                        make_float2(w1 * cc[mt][j][2], w1 * cc[mt][j][3]);
            }
        } else {
#pragma unroll
            for (int j = 0; j < 4; j++) {
                int col = n0 + wn * 32 + j * 8 + 2 * tig;
                *(float2*)(Cout + (size_t)r0 * NCOLS + col) =
                    make_float2(cc[mt][j][0], cc[mt][j][1]);
                *(float2*)(Cout + (size_t)(r0 + 8) * NCOLS + col) =
                    make_float2(cc[mt][j][2], cc[mt][j][3]);
            }
        }
    }
}

// ----------------------------- final combine ---------------------------------
__global__ void k_combine(float* __restrict__ out) {
    size_t base = ((size_t)blockIdx.x * blockDim.x + threadIdx.x) * 4;
    if (base >= (size_t)NTOK * HDIM) return;
    int n = (int)(base >> 11);
    int h = (int)(base & 2047);
    float4 o  = *(float4*)(out + base);
    float4 p0 = *(float4*)&g_partial[(size_t)(2 * n) * HDIM + h];
    float4 p1 = *(float4*)&g_partial[(size_t)(2 * n + 1) * HDIM + h];
    o.x += p0.x + p1.x;
    o.y += p0.y + p1.y;
    o.z += p0.z + p1.z;
    o.w += p0.w + p1.w;
    *(float4*)(out + base) = o;
}

// ----------------------------- launch ----------------------------------------
extern "C" void kernel_launch(void* const* d_in, const int* in_sizes, int n_in,
                              void* d_out, int out_size)
{
    const float* x       = (const float*)d_in[0];
    const float* gate_w  = (const float*)d_in[1];
    const float* w_gate  = (const float*)d_in[2];
    const float* w_up    = (const float*)d_in[3];
    const float* w_down  = (const float*)d_in[4];
    const float* sw_gate = (const float*)d_in[5];
    const float* sw_up   = (const float*)d_in[6];
    const float* sw_down = (const float*)d_in[7];
    float* out = (float*)d_out;

    cudaFuncSetAttribute(k_swiglu_mma<true, IDIM, HDIM>,
                         cudaFuncAttributeMaxDynamicSharedMemorySize, SMEMSZ_MMA);
    cudaFuncSetAttribute(k_swiglu_mma<false, ISH, HDIM>,
                         cudaFuncAttributeMaxDynamicSharedMemorySize, SMEMSZ_MMA);
    cudaFuncSetAttribute(k_down_mma<true, HDIM, IDIM>,
                         cudaFuncAttributeMaxDynamicSharedMemorySize, SMEMSZ_MMA);
    cudaFuncSetAttribute(k_down_mma<false, HDIM, ISH>,
                         cudaFuncAttributeMaxDynamicSharedMemorySize, SMEMSZ_MMA);

    k_reset<<<(CAP + 255) / 256, 256>>>();
    k_gate<<<NTOK, 128>>>(x, gate_w);
    k_count<<<(NTOK * TOPK + 255) / 256, 256>>>();
    k_scan<<<1, 32>>>();
    k_place<<<(NTOK * TOPK + 255) / 256, 256>>>();

    {   // routed SwiGLU -> g_hbuf
        dim3 grid(NTOK / 128, IDIM / 64, NEXP);
        k_swiglu_mma<true, IDIM, HDIM><<<grid, 256, SMEMSZ_MMA>>>(x, w_gate, w_up);
    }
    {   // shared SwiGLU -> g_sbuf
        dim3 grid(NTOK / 128, ISH / 64, 1);
        k_swiglu_mma<false, ISH, HDIM><<<grid, 256, SMEMSZ_MMA>>>(x, sw_gate, sw_up);
    }
    {   // routed down-proj -> g_partial (weighted scatter)
        dim3 grid(NTOK / 128, HDIM / 128, NEXP);
        k_down_mma<true, HDIM, IDIM><<<grid, 256, SMEMSZ_MMA>>>(w_down, out);
    }
    {   // shared down-proj -> out
        dim3 grid(NTOK / 128, HDIM / 128, 1);
        k_down_mma<false, HDIM, ISH><<<grid, 256, SMEMSZ_MMA>>>(sw_down, out);
    }
    k_combine<<<(NTOK * HDIM / 4 + 255) / 256, 256>>>(out);
}

// round 4
// speedup vs baseline: 3.8551x; 2.2357x over previous
#include <cuda_runtime.h>
#include <cuda_fp16.h>
#include <math.h>
#include <stdint.h>

// Problem constants
#define NTOK 2048
#define HDIM 2048
#define IDIM 1408
#define NEXP 8
#define ISH  2816
#define TOPK 2
#define CAP  5120

// ----------------------------- scratch --------------------------------------
__device__ int   g_cnt[NEXP];
__device__ int   g_cnt2[NEXP];
__device__ int   g_off[NEXP];
__device__ int   g_rows_token[CAP];
__device__ int   g_rows_slot[CAP];
__device__ float g_rows_w[CAP];
__device__ int   g_tki[NTOK * TOPK];
__device__ float g_tkw[NTOK * TOPK];
__device__ __half g_hbuf[(size_t)CAP * IDIM];
__device__ __half g_sbuf[(size_t)NTOK * ISH];
__device__ float g_partial[(size_t)NTOK * TOPK * HDIM];

// ----------------------------- helpers --------------------------------------
__device__ __forceinline__ uint32_t smem_u32(const void* p) {
    uint32_t a;
    asm("{ .reg .u64 t; cvta.to.shared.u64 t, %1; cvt.u32.u64 %0, t; }" : "=r"(a) : "l"(p));
    return a;
}
__device__ __forceinline__ uint32_t pk(float x, float y) {
    __half2 h = __floats2half2_rn(x, y);
    return reinterpret_cast<uint32_t&>(h);
}
#define LDSM4(r0, r1, r2, r3, addr) \
    asm volatile("ldmatrix.sync.aligned.m8n8.x4.shared.b16 {%0,%1,%2,%3}, [%4];" \
        : "=r"(r0), "=r"(r1), "=r"(r2), "=r"(r3) : "r"(addr))
#define LDSM2T(r0, r1, addr) \
    asm volatile("ldmatrix.sync.aligned.m8n8.x2.trans.shared.b16 {%0,%1}, [%2];" \
        : "=r"(r0), "=r"(r1) : "r"(addr))
#define MMA16(c, a, b0, b1) \
    asm volatile("mma.sync.aligned.m16n8k16.row.col.f32.f16.f16.f32 " \
        "{%0,%1,%2,%3},{%4,%5,%6,%7},{%8,%9},{%0,%1,%2,%3};" \
        : "+f"((c)[0]), "+f"((c)[1]), "+f"((c)[2]), "+f"((c)[3]) \
        : "r"((a)[0]), "r"((a)[1]), "r"((a)[2]), "r"((a)[3]), "r"(b0), "r"(b1))

// SMEM layout constants (bytes)
// A tile: 128 rows x 32 halves, pitch 80B  -> 10240
// swiglu B: 2 x (32 k-rows x 64 halves, pitch 144B = 4608)
// down   B: 32 k-rows x 128 halves, pitch 272B = 8704
#define A_PITCH   80
#define A_BYTES   10240
#define BSW_PITCH 144
#define BSW_BYTES 4608
#define BDN_PITCH 272
#define BDN_BYTES 8704
#define STG_SW    (A_BYTES + 2 * BSW_BYTES)   // 19456
#define STG_DN    (A_BYTES + BDN_BYTES)       // 18944

// ----------------------------- small kernels ---------------------------------
__global__ void k_reset() {
    int i = blockIdx.x * blockDim.x + threadIdx.x;
    if (i < NEXP) { g_cnt[i] = 0; g_cnt2[i] = 0; }
    if (i < CAP)  { g_rows_token[i] = -1; g_rows_slot[i] = -1; g_rows_w[i] = 0.f; }
}

__global__ void k_gate(const float* __restrict__ x, const float* __restrict__ gw) {
    int n = blockIdx.x;
    int tid = threadIdx.x;
    const float* xr = x + (size_t)n * HDIM;
    float acc[NEXP];
#pragma unroll
    for (int e = 0; e < NEXP; e++) acc[e] = 0.f;
    for (int h = tid; h < HDIM; h += 128) {
        float xv = xr[h];
#pragma unroll
        for (int e = 0; e < NEXP; e++) acc[e] += xv * gw[e * HDIM + h];
    }
    __shared__ float s[NEXP][128];
#pragma unroll
    for (int e = 0; e < NEXP; e++) s[e][tid] = acc[e];
    __syncthreads();
    for (int st = 64; st > 0; st >>= 1) {
        if (tid < st) {
#pragma unroll
            for (int e = 0; e < NEXP; e++) s[e][tid] += s[e][tid + st];
        }
        __syncthreads();
    }
    if (tid == 0) {
        float l[NEXP];
        float m = -1e30f;
#pragma unroll
        for (int e = 0; e < NEXP; e++) { l[e] = s[e][0]; m = fmaxf(m, l[e]); }
        float d = 0.f;
#pragma unroll
        for (int e = 0; e < NEXP; e++) d += expf(l[e] - m);
        int i1 = 0;
#pragma unroll
        for (int e = 1; e < NEXP; e++) if (l[e] > l[i1]) i1 = e;
        int i2 = -1;
#pragma unroll
        for (int e = 0; e < NEXP; e++) {
            if (e == i1) continue;
            if (i2 < 0 || l[e] > l[i2]) i2 = e;
        }
        g_tki[n * 2 + 0] = i1; g_tkw[n * 2 + 0] = expf(l[i1] - m) / d;
        g_tki[n * 2 + 1] = i2; g_tkw[n * 2 + 1] = expf(l[i2] - m) / d;
        atomicAdd(&g_cnt[i1], 1);
        atomicAdd(&g_cnt[i2], 1);
    }
}

__global__ void k_scanplace() {
    int tid = threadIdx.x;
    if (tid == 0) {
        int o = 0;
        for (int e = 0; e < NEXP; e++) {
            g_off[e] = o;
            o += ((g_cnt[e] + 127) / 128) * 128;
        }
    }
    __syncthreads();
    for (int i = tid; i < NTOK * TOPK; i += blockDim.x) {
        int e = g_tki[i];
        int p = g_off[e] + atomicAdd(&g_cnt2[e], 1);
        g_rows_token[p] = i >> 1;
        g_rows_slot[p]  = i;
        g_rows_w[p]     = g_tkw[i];
    }
}

// ----------------------------- SwiGLU fp16 mma GEMM --------------------------
// CTA 128M x 64N vs two B matrices (gate, up). Warps 2x4, warp tile 64x16.
// k-chunk 32 (2 x k16 steps), double buffered. C written as fp16.
template<bool ROUTED, int NCOLS>
__global__ void __launch_bounds__(256) k_swiglu_h(
    const float* __restrict__ X,
    const float* __restrict__ B1g,
    const float* __restrict__ B2g)
{
    constexpr int K = HDIM;
    const int e = blockIdx.z;
    const int cnt = ROUTED ? g_cnt[e] : NTOK;
    const int rowbase = ROUTED ? g_off[e] : 0;
    const int m0 = blockIdx.x * 128;
    if (m0 >= cnt) return;
    const int n0 = blockIdx.y * 64;
    const float* B1 = B1g + (ROUTED ? (size_t)e * K * NCOLS : 0);
    const float* B2 = B2g + (ROUTED ? (size_t)e * K * NCOLS : 0);
    __half* C = ROUTED ? g_hbuf : g_sbuf;

    __shared__ __align__(16) char sm[2 * STG_SW];
    const uint32_t sbase = smem_u32(sm);

    const int tid = threadIdx.x;
    const int lane = tid & 31, wid = tid >> 5;
    const int gid = lane >> 2, tig = lane & 3;
    const int wm = wid >> 2, wn = wid & 3;

    // ---- loader slots ----
    const float* aptr[4];
    int aoff[4];
#pragma unroll
    for (int i = 0; i < 4; i++) {
        int idx = i * 256 + tid;
        int m = idx >> 3, q = idx & 7;
        aoff[i] = m * A_PITCH + q * 8;
        int tok;
        if (ROUTED) { int gr = m0 + m; tok = (gr < cnt) ? g_rows_token[rowbase + gr] : -1; }
        else tok = m0 + m;
        aptr[i] = (tok >= 0) ? (X + (size_t)tok * K + q * 4) : (const float*)0;
    }
    const float *b1p[2], *b2p[2];
    int boff[2];
#pragma unroll
    for (int i = 0; i < 2; i++) {
        int idx = i * 256 + tid;
        int kk = idx >> 4, slot = idx & 15;
        boff[i] = kk * BSW_PITCH + slot * 8;
        b1p[i] = B1 + (size_t)kk * NCOLS + n0 + slot * 4;
        b2p[i] = B2 + (size_t)kk * NCOLS + n0 + slot * 4;
    }

    float4 ra[4], rb1[2], rb2[2];
    float cg[4][2][4], cu[4][2][4];
#pragma unroll
    for (int mt = 0; mt < 4; mt++)
#pragma unroll
        for (int j = 0; j < 2; j++)
#pragma unroll
            for (int c = 0; c < 4; c++) { cg[mt][j][c] = 0.f; cu[mt][j][c] = 0.f; }

    // ldmatrix lane addressing
    const uint32_t a_l = (uint32_t)((wm * 64 + (lane & 15)) * A_PITCH + (lane >> 4) * 16);
    const uint32_t b_l = (uint32_t)((lane & 15) * BSW_PITCH);

    auto LOAD = [&](int ch) {
        int k0 = ch * 32;
#pragma unroll
        for (int i = 0; i < 4; i++)
            ra[i] = aptr[i] ? *(const float4*)(aptr[i] + k0)
                            : make_float4(0.f, 0.f, 0.f, 0.f);
        size_t bo = (size_t)k0 * NCOLS;
#pragma unroll
        for (int i = 0; i < 2; i++) {
            rb1[i] = *(const float4*)(b1p[i] + bo);
            rb2[i] = *(const float4*)(b2p[i] + bo);
        }
    };
    auto STORE = [&](int buf) {
        char* S = sm + buf * STG_SW;
#pragma unroll
        for (int i = 0; i < 4; i++) {
            uint2 v;
            v.x = pk(ra[i].x, ra[i].y); v.y = pk(ra[i].z, ra[i].w);
            *(uint2*)(S + aoff[i]) = v;
        }
#pragma unroll
        for (int i = 0; i < 2; i++) {
            uint2 v1, v2;
            v1.x = pk(rb1[i].x, rb1[i].y); v1.y = pk(rb1[i].z, rb1[i].w);
            v2.x = pk(rb2[i].x, rb2[i].y); v2.y = pk(rb2[i].z, rb2[i].w);
            *(uint2*)(S + A_BYTES + boff[i]) = v1;
            *(uint2*)(S + A_BYTES + BSW_BYTES + boff[i]) = v2;
        }
    };
    auto COMPUTE = [&](int buf) {
        uint32_t base = sbase + buf * STG_SW;
#pragma unroll
        for (int s = 0; s < 2; s++) {
            uint32_t a[4][4];
#pragma unroll
            for (int mt = 0; mt < 4; mt++)
                LDSM4(a[mt][0], a[mt][1], a[mt][2], a[mt][3],
                      base + a_l + mt * (16 * A_PITCH) + s * 32);
#pragma unroll
            for (int j = 0; j < 2; j++) {
                uint32_t g0, g1, u0, u1;
                uint32_t baddr = base + A_BYTES + b_l + s * (16 * BSW_PITCH) + wn * 32 + j * 16;
                LDSM2T(g0, g1, baddr);
                LDSM2T(u0, u1, baddr + BSW_BYTES);
#pragma unroll
                for (int mt = 0; mt < 4; mt++) {
                    MMA16(cg[mt][j], a[mt], g0, g1);
                    MMA16(cu[mt][j], a[mt], u0, u1);
                }
            }
        }
    };

    LOAD(0);
    constexpr int NC = K / 32;
    for (int ch = 0; ch < NC; ch++) {
        STORE(ch & 1);
        __syncthreads();
        if (ch + 1 < NC) LOAD(ch + 1);
        COMPUTE(ch & 1);
        __syncthreads();
    }

    // ---- epilogue: silu(gate)*up -> fp16 ----
#pragma unroll
    for (int mt = 0; mt < 4; mt++) {
        int r0 = m0 + wm * 64 + mt * 16 + gid;
        size_t row0 = (size_t)(rowbase + r0);
        size_t row1 = row0 + 8;
#pragma unroll
        for (int j = 0; j < 2; j++) {
            int col = n0 + wn * 16 + j * 8 + 2 * tig;
            float g0 = cg[mt][j][0], g1 = cg[mt][j][1], g2 = cg[mt][j][2], g3 = cg[mt][j][3];
            float o0 = g0 / (1.f + expf(-g0)) * cu[mt][j][0];
            float o1 = g1 / (1.f + expf(-g1)) * cu[mt][j][1];
            float o2 = g2 / (1.f + expf(-g2)) * cu[mt][j][2];
            float o3 = g3 / (1.f + expf(-g3)) * cu[mt][j][3];
            *(uint32_t*)(C + row0 * NCOLS + col) = pk(o0, o1);
            *(uint32_t*)(C + row1 * NCOLS + col) = pk(o2, o3);
        }
    }
}

// ----------------------------- down-proj fp16 mma GEMM -----------------------
// CTA 128M x 128N, warp tile 64x32. A is fp16 (g_hbuf/g_sbuf).
// ROUTED: weighted scatter into g_partial. !ROUTED: out = acc + p0 + p1 (combine fused).
template<bool ROUTED, int K>
__global__ void __launch_bounds__(256) k_down_h(
    const float* __restrict__ Bg,
    float* __restrict__ out)
{
    const int e = blockIdx.z;
    const int cnt = ROUTED ? g_cnt[e] : NTOK;
    const int rowbase = ROUTED ? g_off[e] : 0;
    const int m0 = blockIdx.x * 128;
    if (m0 >= cnt) return;
    const int n0 = blockIdx.y * 128;
    const float* B = Bg + (ROUTED ? (size_t)e * K * HDIM : 0);
    const __half* A = ROUTED ? g_hbuf : g_sbuf;

    __shared__ __align__(16) char sm[2 * STG_DN];
    const uint32_t sbase = smem_u32(sm);

    const int tid = threadIdx.x;
    const int lane = tid & 31, wid = tid >> 5;
    const int gid = lane >> 2, tig = lane & 3;
    const int wm = wid >> 2, wn = wid & 3;

    // ---- loader slots ----
    const __half* aptr[2];
    int aoff[2];
#pragma unroll
    for (int i = 0; i < 2; i++) {
        int idx = i * 256 + tid;
        int m = idx >> 2, q4 = idx & 3;
        aoff[i] = m * A_PITCH + q4 * 16;
        aptr[i] = A + (size_t)(rowbase + m0 + m) * K + q4 * 8;
    }
    const float* bp[4];
    int boff[4];
#pragma unroll
    for (int i = 0; i < 4; i++) {
        int idx = i * 256 + tid;
        int kk = idx >> 5, slot = idx & 31;
        boff[i] = kk * BDN_PITCH + slot * 8;
        bp[i] = B + (size_t)kk * HDIM + n0 + slot * 4;
    }

    uint4 rah[2];
    float4 rb[4];
    float cc[4][4][4];
#pragma unroll
    for (int mt = 0; mt < 4; mt++)
#pragma unroll
        for (int j = 0; j < 4; j++)
#pragma unroll
            for (int c = 0; c < 4; c++) cc[mt][j][c] = 0.f;

    const uint32_t a_l = (uint32_t)((wm * 64 + (lane & 15)) * A_PITCH + (lane >> 4) * 16);
    const uint32_t b_l = (uint32_t)((lane & 15) * BDN_PITCH);

    auto LOAD = [&](int ch) {
        int k0 = ch * 32;
#pragma unroll
        for (int i = 0; i < 2; i++)
            rah[i] = *(const uint4*)(aptr[i] + k0);
        size_t bo = (size_t)k0 * HDIM;
#pragma unroll
        for (int i = 0; i < 4; i++)
            rb[i] = *(const float4*)(bp[i] + bo);
    };
    auto STORE = [&](int buf) {
        char* S = sm + buf * STG_DN;
#pragma unroll
        for (int i = 0; i < 2; i++)
            *(uint4*)(S + aoff[i]) = rah[i];
#pragma unroll
        for (int i = 0; i < 4; i++) {
            uint2 v;
            v.x = pk(rb[i].x, rb[i].y); v.y = pk(rb[i].z, rb[i].w);
            *(uint2*)(S + A_BYTES + boff[i]) = v;
        }
    };
    auto COMPUTE = [&](int buf) {
        uint32_t base = sbase + buf * STG_DN;
#pragma unroll
        for (int s = 0; s < 2; s++) {
            uint32_t a[4][4];
#pragma unroll
            for (int mt = 0; mt < 4; mt++)
                LDSM4(a[mt][0], a[mt][1], a[mt][2], a[mt][3],
                      base + a_l + mt * (16 * A_PITCH) + s * 32);
#pragma unroll
            for (int j = 0; j < 4; j++) {
                uint32_t b0, b1;
                LDSM2T(b0, b1, base + A_BYTES + b_l + s * (16 * BDN_PITCH) + wn * 64 + j * 16);
#pragma unroll
                for (int mt = 0; mt < 4; mt++)
                    MMA16(cc[mt][j], a[mt], b0, b1);
            }
        }
    };

    LOAD(0);
    constexpr int NC = K / 32;
    for (int ch = 0; ch < NC; ch++) {
        STORE(ch & 1);
        __syncthreads();
        if (ch + 1 < NC) LOAD(ch + 1);
        COMPUTE(ch & 1);
        __syncthreads();
    }

    // ---- epilogue ----
#pragma unroll
    for (int mt = 0; mt < 4; mt++) {
        int r0 = m0 + wm * 64 + mt * 16 + gid;
        if (ROUTED) {
            int gr0 = rowbase + r0, gr1 = gr0 + 8;
            int s0 = g_rows_slot[gr0], s1 = g_rows_slot[gr1];
            float w0 = g_rows_w[gr0],  w1 = g_rows_w[gr1];
#pragma unroll
            for (int j = 0; j < 4; j++) {
                int col = n0 + wn * 32 + j * 8 + 2 * tig;
                if (s0 >= 0)
                    *(float2*)(g_partial + (size_t)s0 * HDIM + col) =
                        make_float2(w0 * cc[mt][j][0], w0 * cc[mt][j][1]);
                if (s1 >= 0)
                    *(float2*)(g_partial + (size_t)s1 * HDIM + col) =
                        make_float2(w1 * cc[mt][j][2], w1 * cc[mt][j][3]);
            }
        } else {
            int r1 = r0 + 8;
#pragma unroll
            for (int j = 0; j < 4; j++) {
                int col = n0 + wn * 32 + j * 8 + 2 * tig;
                float2 p00 = *(const float2*)(g_partial + (size_t)(2 * r0) * HDIM + col);
                float2 p01 = *(const float2*)(g_partial + (size_t)(2 * r0 + 1) * HDIM + col);
                float2 p10 = *(const float2*)(g_partial + (size_t)(2 * r1) * HDIM + col);
                float2 p11 = *(const float2*)(g_partial + (size_t)(2 * r1 + 1) * HDIM + col);
                *(float2*)(out + (size_t)r0 * HDIM + col) =
                    make_float2(cc[mt][j][0] + p00.x + p01.x,
                                cc[mt][j][1] + p00.y + p01.y);
                *(float2*)(out + (size_t)r1 * HDIM + col) =
                    make_float2(cc[mt][j][2] + p10.x + p11.x,
                                cc[mt][j][3] + p10.y + p11.y);
            }
        }
    }
}

// ----------------------------- launch ----------------------------------------
extern "C" void kernel_launch(void* const* d_in, const int* in_sizes, int n_in,
                              void* d_out, int out_size)
{
    const float* x       = (const float*)d_in[0];
    const float* gate_w  = (const float*)d_in[1];
    const float* w_gate  = (const float*)d_in[2];
    const float* w_up    = (const float*)d_in[3];
    const float* w_down  = (const float*)d_in[4];
    const float* sw_gate = (const float*)d_in[5];
    const float* sw_up   = (const float*)d_in[6];
    const float* sw_down = (const float*)d_in[7];
    float* out = (float*)d_out;

    k_reset<<<(CAP + 255) / 256, 256>>>();
    k_gate<<<NTOK, 128>>>(x, gate_w);
    k_scanplace<<<1, 256>>>();

    {   // routed SwiGLU -> g_hbuf (fp16)
        dim3 grid(NTOK / 128, IDIM / 64, NEXP);
        k_swiglu_h<true, IDIM><<<grid, 256>>>(x, w_gate, w_up);
    }
    {   // shared SwiGLU -> g_sbuf (fp16)
        dim3 grid(NTOK / 128, ISH / 64, 1);
        k_swiglu_h<false, ISH><<<grid, 256>>>(x, sw_gate, sw_up);
    }
    {   // routed down-proj -> g_partial (weighted scatter)
        dim3 grid(NTOK / 128, HDIM / 128, NEXP);
        k_down_h<true, IDIM><<<grid, 256>>>(w_down, out);
    }
    {   // shared down-proj -> out (combine fused: out = acc + p0 + p1)
        dim3 grid(NTOK / 128, HDIM / 128, 1);
        k_down_h<false, ISH><<<grid, 256>>>(sw_down, out);
    }
}

// round 5
// speedup vs baseline: 4.9407x; 1.2816x over previous
#include <cuda_runtime.h>
#include <cuda_fp16.h>
#include <math.h>
#include <stdint.h>

// Problem constants
#define NTOK 2048
#define HDIM 2048
#define IDIM 1408
#define NEXP 8
#define ISH  2816
#define TOPK 2
#define CAP  5120

// ----------------------------- scratch --------------------------------------
__device__ int   g_cnt[NEXP];
__device__ int   g_cnt2[NEXP];
__device__ int   g_off[NEXP];
__device__ int   g_rows_token[CAP];
__device__ int   g_rows_slot[CAP];
__device__ float g_rows_w[CAP];
__device__ int   g_tki[NTOK * TOPK];
__device__ float g_tkw[NTOK * TOPK];
__device__ __half g_hbuf[(size_t)CAP * IDIM];
__device__ __half g_sbuf[(size_t)NTOK * ISH];
__device__ float g_partial[(size_t)NTOK * TOPK * HDIM];

// fp16 copies of inputs (converted per call)
__device__ __half g_xh [(size_t)NTOK * HDIM];
__device__ __half g_wgh[(size_t)NEXP * HDIM * IDIM];
__device__ __half g_wuh[(size_t)NEXP * HDIM * IDIM];
__device__ __half g_wdh[(size_t)NEXP * IDIM * HDIM];
__device__ __half g_sgh[(size_t)HDIM * ISH];
__device__ __half g_suh[(size_t)HDIM * ISH];
__device__ __half g_sdh[(size_t)ISH * HDIM];

// ----------------------------- helpers --------------------------------------
__device__ __forceinline__ uint32_t smem_u32(const void* p) {
    uint32_t a;
    asm("{ .reg .u64 t; cvta.to.shared.u64 t, %1; cvt.u32.u64 %0, t; }" : "=r"(a) : "l"(p));
    return a;
}
__device__ __forceinline__ uint32_t pk(float x, float y) {
    __half2 h = __floats2half2_rn(x, y);
    return reinterpret_cast<uint32_t&>(h);
}
#define LDSM4(r0, r1, r2, r3, addr) \
    asm volatile("ldmatrix.sync.aligned.m8n8.x4.shared.b16 {%0,%1,%2,%3}, [%4];" \
        : "=r"(r0), "=r"(r1), "=r"(r2), "=r"(r3) : "r"(addr))
#define LDSM2T(r0, r1, addr) \
    asm volatile("ldmatrix.sync.aligned.m8n8.x2.trans.shared.b16 {%0,%1}, [%2];" \
        : "=r"(r0), "=r"(r1) : "r"(addr))
#define MMA16(c, a, b0, b1) \
    asm volatile("mma.sync.aligned.m16n8k16.row.col.f32.f16.f16.f32 " \
        "{%0,%1,%2,%3},{%4,%5,%6,%7},{%8,%9},{%0,%1,%2,%3};" \
        : "+f"((c)[0]), "+f"((c)[1]), "+f"((c)[2]), "+f"((c)[3]) \
        : "r"((a)[0]), "r"((a)[1]), "r"((a)[2]), "r"((a)[3]), "r"(b0), "r"(b1))
#define CPA16(dst, src) \
    asm volatile("cp.async.cg.shared.global [%0], [%1], 16;" :: "r"(dst), "l"(src))
#define CPCOMMIT() asm volatile("cp.async.commit_group;" ::: "memory")
#define CPWAIT3()  asm volatile("cp.async.wait_group 3;" ::: "memory")

// SMEM layout (bytes). A: 128 rows x 32 halves, pitch 80. B pitches padded.
#define A_PITCH   80
#define A_BYTES   10240
#define BSW_PITCH 144
#define BSW_BYTES 4608
#define BDN_PITCH 272
#define BDN_BYTES 8704
#define STG_SW    (A_BYTES + 2 * BSW_BYTES)   // 19456
#define STG_DN    (A_BYTES + BDN_BYTES)       // 18944
#define NSTG      5
#define SMEM_SW   (NSTG * STG_SW)             // 97280
#define SMEM_DN   (NSTG * STG_DN)             // 94720

// ----------------------------- fp32 -> fp16 convert --------------------------
template<int ID>
__global__ void k_cvt(const float4* __restrict__ src, int n4) {
    __half* dst =
        ID == 0 ? g_xh  : ID == 1 ? g_wgh : ID == 2 ? g_wuh :
        ID == 3 ? g_wdh : ID == 4 ? g_sgh : ID == 5 ? g_suh : g_sdh;
    int i = blockIdx.x * blockDim.x + threadIdx.x;
    if (i < n4) {
        float4 v = src[i];
        uint2 o;
        o.x = pk(v.x, v.y); o.y = pk(v.z, v.w);
        *(uint2*)(dst + (size_t)i * 4) = o;
    }
}

// ----------------------------- small kernels ---------------------------------
__global__ void k_reset() {
    int i = blockIdx.x * blockDim.x + threadIdx.x;
    if (i < NEXP) { g_cnt[i] = 0; g_cnt2[i] = 0; }
    if (i < CAP)  { g_rows_token[i] = 0; g_rows_slot[i] = -1; g_rows_w[i] = 0.f; }
}

__global__ void k_gate(const float* __restrict__ x, const float* __restrict__ gw) {
    int n = blockIdx.x;
    int tid = threadIdx.x;
    const float* xr = x + (size_t)n * HDIM;
    float acc[NEXP];
#pragma unroll
    for (int e = 0; e < NEXP; e++) acc[e] = 0.f;
    for (int h = tid; h < HDIM; h += 128) {
        float xv = xr[h];
#pragma unroll
        for (int e = 0; e < NEXP; e++) acc[e] += xv * gw[e * HDIM + h];
    }
    __shared__ float s[NEXP][128];
#pragma unroll
    for (int e = 0; e < NEXP; e++) s[e][tid] = acc[e];
    __syncthreads();
    for (int st = 64; st > 0; st >>= 1) {
        if (tid < st) {
#pragma unroll
            for (int e = 0; e < NEXP; e++) s[e][tid] += s[e][tid + st];
        }
        __syncthreads();
    }
    if (tid == 0) {
        float l[NEXP];
        float m = -1e30f;
#pragma unroll
        for (int e = 0; e < NEXP; e++) { l[e] = s[e][0]; m = fmaxf(m, l[e]); }
        float d = 0.f;
#pragma unroll
        for (int e = 0; e < NEXP; e++) d += expf(l[e] - m);
        int i1 = 0;
#pragma unroll
        for (int e = 1; e < NEXP; e++) if (l[e] > l[i1]) i1 = e;
        int i2 = -1;
#pragma unroll
        for (int e = 0; e < NEXP; e++) {
            if (e == i1) continue;
            if (i2 < 0 || l[e] > l[i2]) i2 = e;
        }
        g_tki[n * 2 + 0] = i1; g_tkw[n * 2 + 0] = expf(l[i1] - m) / d;
        g_tki[n * 2 + 1] = i2; g_tkw[n * 2 + 1] = expf(l[i2] - m) / d;
        atomicAdd(&g_cnt[i1], 1);
        atomicAdd(&g_cnt[i2], 1);
    }
}

__global__ void k_scanplace() {
    int tid = threadIdx.x;
    if (tid == 0) {
        int o = 0;
        for (int e = 0; e < NEXP; e++) {
            g_off[e] = o;
            o += ((g_cnt[e] + 127) / 128) * 128;
        }
    }
    __syncthreads();
    for (int i = tid; i < NTOK * TOPK; i += blockDim.x) {
        int e = g_tki[i];
        int p = g_off[e] + atomicAdd(&g_cnt2[e], 1);
        g_rows_token[p] = i >> 1;
        g_rows_slot[p]  = i;
        g_rows_w[p]     = g_tkw[i];
    }
}

// ----------------------------- SwiGLU fp16 mma GEMM --------------------------
// CTA 128M x 64N vs two B matrices. 5-stage cp.async pipeline, k-chunk 32.
template<bool ROUTED, int NCOLS>
__global__ void __launch_bounds__(256) k_swiglu_h()
{
    constexpr int K = HDIM;
    const int e = blockIdx.z;
    const int cnt = ROUTED ? g_cnt[e] : NTOK;
    const int rowbase = ROUTED ? g_off[e] : 0;
    const int m0 = blockIdx.x * 128;
    if (m0 >= cnt) return;
    const int n0 = blockIdx.y * 64;
    const __half* B1 = (ROUTED ? g_wgh : g_sgh) + (ROUTED ? (size_t)e * K * NCOLS : 0);
    const __half* B2 = (ROUTED ? g_wuh : g_suh) + (ROUTED ? (size_t)e * K * NCOLS : 0);
    __half* C = ROUTED ? g_hbuf : g_sbuf;

    extern __shared__ __align__(16) char sm[];
    const uint32_t sbase = smem_u32(sm);

    const int tid = threadIdx.x;
    const int lane = tid & 31, wid = tid >> 5;
    const int gid = lane >> 2, tig = lane & 3;
    const int wm = wid >> 2, wn = wid & 3;

    // ---- cp.async slots: A = 2 segs/thread, B = 1 seg/thread/matrix ----
    const __half* aseg[2];
    uint32_t aoff[2];
#pragma unroll
    for (int i = 0; i < 2; i++) {
        int idx = i * 256 + tid;
        int m = idx >> 2, q = idx & 3;
        aoff[i] = (uint32_t)(m * A_PITCH + q * 16);
        int tok;
        if (ROUTED) { int gr = m0 + m; tok = (gr < cnt) ? g_rows_token[rowbase + gr] : 0; }
        else tok = m0 + m;
        aseg[i] = g_xh + (size_t)tok * K + q * 8;
    }
    const int bkk = tid >> 3, bslot = tid & 7;
    const uint32_t boff = (uint32_t)(bkk * BSW_PITCH + bslot * 16);
    const __half* b1s = B1 + (size_t)bkk * NCOLS + n0 + bslot * 8;
    const __half* b2s = B2 + (size_t)bkk * NCOLS + n0 + bslot * 8;

    float cg[4][2][4], cu[4][2][4];
#pragma unroll
    for (int mt = 0; mt < 4; mt++)
#pragma unroll
        for (int j = 0; j < 2; j++)
#pragma unroll
            for (int c = 0; c < 4; c++) { cg[mt][j][c] = 0.f; cu[mt][j][c] = 0.f; }

    const uint32_t a_l = (uint32_t)((wm * 64 + (lane & 15)) * A_PITCH + (lane >> 4) * 16);
    const uint32_t b_l = (uint32_t)((lane & 15) * BSW_PITCH);

    auto ISSUE = [&](int ch, int buf) {
        uint32_t s0 = sbase + buf * STG_SW;
        size_t k0 = (size_t)ch * 32;
        CPA16(s0 + aoff[0], aseg[0] + k0);
        CPA16(s0 + aoff[1], aseg[1] + k0);
        CPA16(s0 + A_BYTES + boff, b1s + k0 * NCOLS);
        CPA16(s0 + A_BYTES + BSW_BYTES + boff, b2s + k0 * NCOLS);
    };
    auto COMPUTE = [&](int buf) {
        uint32_t base = sbase + buf * STG_SW;
#pragma unroll
        for (int s = 0; s < 2; s++) {
            uint32_t a[4][4];
#pragma unroll
            for (int mt = 0; mt < 4; mt++)
                LDSM4(a[mt][0], a[mt][1], a[mt][2], a[mt][3],
                      base + a_l + mt * (16 * A_PITCH) + s * 32);
#pragma unroll
            for (int j = 0; j < 2; j++) {
                uint32_t g0, g1, u0, u1;
                uint32_t baddr = base + A_BYTES + b_l + s * (16 * BSW_PITCH) + wn * 32 + j * 16;
                LDSM2T(g0, g1, baddr);
                LDSM2T(u0, u1, baddr + BSW_BYTES);
#pragma unroll
                for (int mt = 0; mt < 4; mt++) {
                    MMA16(cg[mt][j], a[mt], g0, g1);
                    MMA16(cu[mt][j], a[mt], u0, u1);
                }
            }
        }
    };

    constexpr int NC = K / 32;
#pragma unroll
    for (int s = 0; s < NSTG - 1; s++) { ISSUE(s, s); CPCOMMIT(); }
    for (int ch = 0; ch < NC; ch++) {
        CPWAIT3();
        __syncthreads();
        int nx = ch + NSTG - 1;
        if (nx < NC) ISSUE(nx, nx % NSTG);
        CPCOMMIT();
        COMPUTE(ch % NSTG);
    }

    // ---- epilogue: silu(gate)*up -> fp16 ----
#pragma unroll
    for (int mt = 0; mt < 4; mt++) {
        int r0 = m0 + wm * 64 + mt * 16 + gid;
        size_t row0 = (size_t)(rowbase + r0);
        size_t row1 = row0 + 8;
#pragma unroll
        for (int j = 0; j < 2; j++) {
            int col = n0 + wn * 16 + j * 8 + 2 * tig;
            float g0 = cg[mt][j][0], g1 = cg[mt][j][1], g2 = cg[mt][j][2], g3 = cg[mt][j][3];
            float o0 = g0 / (1.f + expf(-g0)) * cu[mt][j][0];
            float o1 = g1 / (1.f + expf(-g1)) * cu[mt][j][1];
            float o2 = g2 / (1.f + expf(-g2)) * cu[mt][j][2];
            float o3 = g3 / (1.f + expf(-g3)) * cu[mt][j][3];
            *(uint32_t*)(C + row0 * NCOLS + col) = pk(o0, o1);
            *(uint32_t*)(C + row1 * NCOLS + col) = pk(o2, o3);
        }
    }
}

// ----------------------------- down-proj fp16 mma GEMM -----------------------
// CTA 128M x 128N. 5-stage cp.async pipeline.
template<bool ROUTED, int K>
__global__ void __launch_bounds__(256) k_down_h(float* __restrict__ out)
{
    const int e = blockIdx.z;
    const int cnt = ROUTED ? g_cnt[e] : NTOK;
    const int rowbase = ROUTED ? g_off[e] : 0;
    const int m0 = blockIdx.x * 128;
    if (m0 >= cnt) return;
    const int n0 = blockIdx.y * 128;
    const __half* B = (ROUTED ? g_wdh : g_sdh) + (ROUTED ? (size_t)e * K * HDIM : 0);
    const __half* A = ROUTED ? g_hbuf : g_sbuf;

    extern __shared__ __align__(16) char sm[];
    const uint32_t sbase = smem_u32(sm);

    const int tid = threadIdx.x;
    const int lane = tid & 31, wid = tid >> 5;
    const int gid = lane >> 2, tig = lane & 3;
    const int wm = wid >> 2, wn = wid & 3;

    // ---- cp.async slots: A = 2 segs/thread, B = 2 segs/thread ----
    const __half* aseg[2];
    uint32_t aoff[2];
#pragma unroll
    for (int i = 0; i < 2; i++) {
        int idx = i * 256 + tid;
        int m = idx >> 2, q = idx & 3;
        aoff[i] = (uint32_t)(m * A_PITCH + q * 16);
        aseg[i] = A + (size_t)(rowbase + m0 + m) * K + q * 8;
    }
    const __half* bseg[2];
    uint32_t boff[2];
#pragma unroll
    for (int i = 0; i < 2; i++) {
        int idx = i * 256 + tid;
        int kk = idx >> 4, slot = idx & 15;
        boff[i] = (uint32_t)(kk * BDN_PITCH + slot * 16);
        bseg[i] = B + (size_t)kk * HDIM + n0 + slot * 8;
    }

    float cc[4][4][4];
#pragma unroll
    for (int mt = 0; mt < 4; mt++)
#pragma unroll
        for (int j = 0; j < 4; j++)
#pragma unroll
            for (int c = 0; c < 4; c++) cc[mt][j][c] = 0.f;

    const uint32_t a_l = (uint32_t)((wm * 64 + (lane & 15)) * A_PITCH + (lane >> 4) * 16);
    const uint32_t b_l = (uint32_t)((lane & 15) * BDN_PITCH);

    auto ISSUE = [&](int ch, int buf) {
        uint32_t s0 = sbase + buf * STG_DN;
        size_t k0 = (size_t)ch * 32;
        CPA16(s0 + aoff[0], aseg[0] + k0);
        CPA16(s0 + aoff[1], aseg[1] + k0);
        CPA16(s0 + A_BYTES + boff[0], bseg[0] + k0 * HDIM);
        CPA16(s0 + A_BYTES + boff[1], bseg[1] + k0 * HDIM);
    };
    auto COMPUTE = [&](int buf) {
        uint32_t base = sbase + buf * STG_DN;
#pragma unroll
        for (int s = 0; s < 2; s++) {
            uint32_t a[4][4];
#pragma unroll
            for (int mt = 0; mt < 4; mt++)
                LDSM4(a[mt][0], a[mt][1], a[mt][2], a[mt][3],
                      base + a_l + mt * (16 * A_PITCH) + s * 32);
#pragma unroll
            for (int j = 0; j < 4; j++) {
                uint32_t b0, b1;
                LDSM2T(b0, b1, base + A_BYTES + b_l + s * (16 * BDN_PITCH) + wn * 64 + j * 16);
#pragma unroll
                for (int mt = 0; mt < 4; mt++)
                    MMA16(cc[mt][j], a[mt], b0, b1);
            }
        }
    };

    constexpr int NC = K / 32;
#pragma unroll
    for (int s = 0; s < NSTG - 1; s++) { ISSUE(s, s); CPCOMMIT(); }
    for (int ch = 0; ch < NC; ch++) {
        CPWAIT3();
        __syncthreads();
        int nx = ch + NSTG - 1;
        if (nx < NC) ISSUE(nx, nx % NSTG);
        CPCOMMIT();
        COMPUTE(ch % NSTG);
    }

    // ---- epilogue ----
#pragma unroll
    for (int mt = 0; mt < 4; mt++) {
        int r0 = m0 + wm * 64 + mt * 16 + gid;
        if (ROUTED) {
            int gr0 = rowbase + r0, gr1 = gr0 + 8;
            int s0 = g_rows_slot[gr0], s1 = g_rows_slot[gr1];
            float w0 = g_rows_w[gr0],  w1 = g_rows_w[gr1];
#pragma unroll
            for (int j = 0; j < 4; j++) {
                int col = n0 + wn * 32 + j * 8 + 2 * tig;
                if (s0 >= 0)
                    *(float2*)(g_partial + (size_t)s0 * HDIM + col) =
                        make_float2(w0 * cc[mt][j][0], w0 * cc[mt][j][1]);
                if (s1 >= 0)
                    *(float2*)(g_partial + (size_t)s1 * HDIM + col) =
                        make_float2(w1 * cc[mt][j][2], w1 * cc[mt][j][3]);
            }
        } else {
            int r1 = r0 + 8;
#pragma unroll
            for (int j = 0; j < 4; j++) {
                int col = n0 + wn * 32 + j * 8 + 2 * tig;
                float2 p00 = *(const float2*)(g_partial + (size_t)(2 * r0) * HDIM + col);
                float2 p01 = *(const float2*)(g_partial + (size_t)(2 * r0 + 1) * HDIM + col);
                float2 p10 = *(const float2*)(g_partial + (size_t)(2 * r1) * HDIM + col);
                float2 p11 = *(const float2*)(g_partial + (size_t)(2 * r1 + 1) * HDIM + col);
                *(float2*)(out + (size_t)r0 * HDIM + col) =
                    make_float2(cc[mt][j][0] + p00.x + p01.x,
                                cc[mt][j][1] + p00.y + p01.y);
                *(float2*)(out + (size_t)r1 * HDIM + col) =
                    make_float2(cc[mt][j][2] + p10.x + p11.x,
                                cc[mt][j][3] + p10.y + p11.y);
            }
        }
    }
}

// ----------------------------- launch ----------------------------------------
extern "C" void kernel_launch(void* const* d_in, const int* in_sizes, int n_in,
                              void* d_out, int out_size)
{
    const float* x       = (const float*)d_in[0];
    const float* gate_w  = (const float*)d_in[1];
    const float* w_gate  = (const float*)d_in[2];
    const float* w_up    = (const float*)d_in[3];
    const float* w_down  = (const float*)d_in[4];
    const float* sw_gate = (const float*)d_in[5];
    const float* sw_up   = (const float*)d_in[6];
    const float* sw_down = (const float*)d_in[7];
    float* out = (float*)d_out;

    cudaFuncSetAttribute(k_swiglu_h<true, IDIM>,
                         cudaFuncAttributeMaxDynamicSharedMemorySize, SMEM_SW);
    cudaFuncSetAttribute(k_swiglu_h<false, ISH>,
                         cudaFuncAttributeMaxDynamicSharedMemorySize, SMEM_SW);
    cudaFuncSetAttribute(k_down_h<true, IDIM>,
                         cudaFuncAttributeMaxDynamicSharedMemorySize, SMEM_DN);
    cudaFuncSetAttribute(k_down_h<false, ISH>,
                         cudaFuncAttributeMaxDynamicSharedMemorySize, SMEM_DN);

    k_reset<<<(CAP + 255) / 256, 256>>>();
    k_gate<<<NTOK, 128>>>(x, gate_w);
    k_scanplace<<<1, 256>>>();

    // fp32 -> fp16 conversions
    {
        int n4;
        n4 = NTOK * HDIM / 4;
        k_cvt<0><<<(n4 + 255) / 256, 256>>>((const float4*)x, n4);
        n4 = NEXP * HDIM * IDIM / 4;
        k_cvt<1><<<(n4 + 255) / 256, 256>>>((const float4*)w_gate, n4);
        k_cvt<2><<<(n4 + 255) / 256, 256>>>((const float4*)w_up, n4);
        k_cvt<3><<<(n4 + 255) / 256, 256>>>((const float4*)w_down, n4);
        n4 = HDIM * ISH / 4;
        k_cvt<4><<<(n4 + 255) / 256, 256>>>((const float4*)sw_gate, n4);
        k_cvt<5><<<(n4 + 255) / 256, 256>>>((const float4*)sw_up, n4);
        n4 = ISH * HDIM / 4;
        k_cvt<6><<<(n4 + 255) / 256, 256>>>((const float4*)sw_down, n4);
    }

    {   // routed SwiGLU -> g_hbuf (fp16)
        dim3 grid(NTOK / 128, IDIM / 64, NEXP);
        k_swiglu_h<true, IDIM><<<grid, 256, SMEM_SW>>>();
    }
    {   // shared SwiGLU -> g_sbuf (fp16)
        dim3 grid(NTOK / 128, ISH / 64, 1);
        k_swiglu_h<false, ISH><<<grid, 256, SMEM_SW>>>();
    }
    {   // routed down-proj -> g_partial (weighted scatter)
        dim3 grid(NTOK / 128, HDIM / 128, NEXP);
        k_down_h<true, IDIM><<<grid, 256, SMEM_DN>>>(out);
    }
    {   // shared down-proj -> out (combine fused)
        dim3 grid(NTOK / 128, HDIM / 128, 1);
        k_down_h<false, ISH><<<grid, 256, SMEM_DN>>>(out);
    }
}

// round 6
// speedup vs baseline: 5.6874x; 1.1511x over previous
#include <cuda_runtime.h>
#include <cuda_fp16.h>
#include <math.h>
#include <stdint.h>

// Problem constants
#define NTOK 2048
#define HDIM 2048
#define IDIM 1408
#define NEXP 8
#define ISH  2816
#define TOPK 2
#define CAP  5120

// ----------------------------- scratch --------------------------------------
__device__ int   g_cnt[NEXP];
__device__ int   g_cnt2[NEXP];
__device__ int   g_off[NEXP];
__device__ int   g_rows_token[CAP];
__device__ int   g_rows_slot[CAP];
__device__ float g_rows_w[CAP];
__device__ int   g_tki[NTOK * TOPK];
__device__ float g_tkw[NTOK * TOPK];
__device__ __half g_hbuf[(size_t)CAP * IDIM];
__device__ __half g_sbuf[(size_t)NTOK * ISH];
__device__ float g_partial[(size_t)NTOK * TOPK * HDIM];

// fp16 copies of inputs (converted per call)
__device__ __half g_xh [(size_t)NTOK * HDIM];
__device__ __half g_wgh[(size_t)NEXP * HDIM * IDIM];
__device__ __half g_wuh[(size_t)NEXP * HDIM * IDIM];
__device__ __half g_wdh[(size_t)NEXP * IDIM * HDIM];
__device__ __half g_sgh[(size_t)HDIM * ISH];
__device__ __half g_suh[(size_t)HDIM * ISH];
__device__ __half g_sdh[(size_t)ISH * HDIM];

// ----------------------------- helpers --------------------------------------
__device__ __forceinline__ uint32_t smem_u32(const void* p) {
    uint32_t a;
    asm("{ .reg .u64 t; cvta.to.shared.u64 t, %1; cvt.u32.u64 %0, t; }" : "=r"(a) : "l"(p));
    return a;
}
__device__ __forceinline__ uint32_t pk(float x, float y) {
    __half2 h = __floats2half2_rn(x, y);
    return reinterpret_cast<uint32_t&>(h);
}
#define LDSM4(r0, r1, r2, r3, addr) \
    asm volatile("ldmatrix.sync.aligned.m8n8.x4.shared.b16 {%0,%1,%2,%3}, [%4];" \
        : "=r"(r0), "=r"(r1), "=r"(r2), "=r"(r3) : "r"(addr))
#define LDSM2T(r0, r1, addr) \
    asm volatile("ldmatrix.sync.aligned.m8n8.x2.trans.shared.b16 {%0,%1}, [%2];" \
        : "=r"(r0), "=r"(r1) : "r"(addr))
#define MMA16(c, a, b0, b1) \
    asm volatile("mma.sync.aligned.m16n8k16.row.col.f32.f16.f16.f32 " \
        "{%0,%1,%2,%3},{%4,%5,%6,%7},{%8,%9},{%0,%1,%2,%3};" \
        : "+f"((c)[0]), "+f"((c)[1]), "+f"((c)[2]), "+f"((c)[3]) \
        : "r"((a)[0]), "r"((a)[1]), "r"((a)[2]), "r"((a)[3]), "r"(b0), "r"(b1))
#define CPA16(dst, src) \
    asm volatile("cp.async.cg.shared.global [%0], [%1], 16;" :: "r"(dst), "l"(src))
#define CPCOMMIT() asm volatile("cp.async.commit_group;" ::: "memory")
#define CPWAIT2()  asm volatile("cp.async.wait_group 2;" ::: "memory")

// SMEM layout (bytes). A: 128 rows x 32 halves, pitch 80. B pitches padded.
#define A_PITCH   80
#define A_BYTES   10240
#define BSW_PITCH 144
#define BSW_BYTES 4608
#define BDN_PITCH 272
#define BDN_BYTES 8704
#define STG_SW    (A_BYTES + 2 * BSW_BYTES)   // 19456
#define STG_DN    (A_BYTES + BDN_BYTES)       // 18944
#define NSTG      4
#define SMEM_SW   (NSTG * STG_SW)             // 77824
#define SMEM_DN   (NSTG * STG_DN)             // 75776

// ----------------------------- fp32 -> fp16 convert --------------------------
// grid-stride, 8 floats (2 float4) per thread per step
template<int ID>
__global__ void __launch_bounds__(256) k_cvt(const float4* __restrict__ src, int n8) {
    __half* dst =
        ID == 0 ? g_xh  : ID == 1 ? g_wgh : ID == 2 ? g_wuh :
        ID == 3 ? g_wdh : ID == 4 ? g_sgh : ID == 5 ? g_suh : g_sdh;
    int stride = gridDim.x * blockDim.x;
    for (int i = blockIdx.x * blockDim.x + threadIdx.x; i < n8; i += stride) {
        float4 v0 = src[2 * i];
        float4 v1 = src[2 * i + 1];
        uint4 o;
        o.x = pk(v0.x, v0.y); o.y = pk(v0.z, v0.w);
        o.z = pk(v1.x, v1.y); o.w = pk(v1.z, v1.w);
        *(uint4*)(dst + (size_t)i * 8) = o;
    }
}

// ----------------------------- small kernels ---------------------------------
__global__ void k_reset() {
    int i = blockIdx.x * blockDim.x + threadIdx.x;
    if (i < NEXP) { g_cnt[i] = 0; g_cnt2[i] = 0; }
    if (i < CAP)  { g_rows_token[i] = 0; g_rows_slot[i] = -1; g_rows_w[i] = 0.f; }
}

__global__ void k_gate(const float* __restrict__ x, const float* __restrict__ gw) {
    int n = blockIdx.x;
    int tid = threadIdx.x;
    const float* xr = x + (size_t)n * HDIM;
    float acc[NEXP];
#pragma unroll
    for (int e = 0; e < NEXP; e++) acc[e] = 0.f;
    for (int h = tid; h < HDIM; h += 128) {
        float xv = xr[h];
#pragma unroll
        for (int e = 0; e < NEXP; e++) acc[e] += xv * gw[e * HDIM + h];
    }
    __shared__ float s[NEXP][128];
#pragma unroll
    for (int e = 0; e < NEXP; e++) s[e][tid] = acc[e];
    __syncthreads();
    for (int st = 64; st > 0; st >>= 1) {
        if (tid < st) {
#pragma unroll
            for (int e = 0; e < NEXP; e++) s[e][tid] += s[e][tid + st];
        }
        __syncthreads();
    }
    if (tid == 0) {
        float l[NEXP];
        float m = -1e30f;
#pragma unroll
        for (int e = 0; e < NEXP; e++) { l[e] = s[e][0]; m = fmaxf(m, l[e]); }
        float d = 0.f;
#pragma unroll
        for (int e = 0; e < NEXP; e++) d += expf(l[e] - m);
        int i1 = 0;
#pragma unroll
        for (int e = 1; e < NEXP; e++) if (l[e] > l[i1]) i1 = e;
        int i2 = -1;
#pragma unroll
        for (int e = 0; e < NEXP; e++) {
            if (e == i1) continue;
            if (i2 < 0 || l[e] > l[i2]) i2 = e;
        }
        g_tki[n * 2 + 0] = i1; g_tkw[n * 2 + 0] = expf(l[i1] - m) / d;
        g_tki[n * 2 + 1] = i2; g_tkw[n * 2 + 1] = expf(l[i2] - m) / d;
        atomicAdd(&g_cnt[i1], 1);
        atomicAdd(&g_cnt[i2], 1);
    }
}

__global__ void k_scanplace() {
    int tid = threadIdx.x;
    if (tid == 0) {
        int o = 0;
        for (int e = 0; e < NEXP; e++) {
            g_off[e] = o;
            o += ((g_cnt[e] + 127) / 128) * 128;
        }
    }
    __syncthreads();
    for (int i = tid; i < NTOK * TOPK; i += blockDim.x) {
        int e = g_tki[i];
        int p = g_off[e] + atomicAdd(&g_cnt2[e], 1);
        g_rows_token[p] = i >> 1;
        g_rows_slot[p]  = i;
        g_rows_w[p]     = g_tkw[i];
    }
}

// ----------------------------- SwiGLU fp16 mma GEMM --------------------------
// CTA 128M x 64N vs two B matrices. 4-stage cp.async pipeline, k-chunk 32.
template<bool ROUTED, int NCOLS>
__global__ void __launch_bounds__(256, 2) k_swiglu_h()
{
    constexpr int K = HDIM;
    const int e = blockIdx.z;
    const int cnt = ROUTED ? g_cnt[e] : NTOK;
    const int rowbase = ROUTED ? g_off[e] : 0;
    const int m0 = blockIdx.x * 128;
    if (m0 >= cnt) return;
    const int n0 = blockIdx.y * 64;
    const __half* B1 = (ROUTED ? g_wgh : g_sgh) + (ROUTED ? (size_t)e * K * NCOLS : 0);
    const __half* B2 = (ROUTED ? g_wuh : g_suh) + (ROUTED ? (size_t)e * K * NCOLS : 0);
    __half* C = ROUTED ? g_hbuf : g_sbuf;

    extern __shared__ __align__(16) char sm[];
    const uint32_t sbase = smem_u32(sm);

    const int tid = threadIdx.x;
    const int lane = tid & 31, wid = tid >> 5;
    const int gid = lane >> 2, tig = lane & 3;
    const int wm = wid >> 2, wn = wid & 3;

    // ---- cp.async slots: A = 2 segs/thread, B = 1 seg/thread/matrix ----
    const __half* aseg[2];
    uint32_t aoff[2];
#pragma unroll
    for (int i = 0; i < 2; i++) {
        int idx = i * 256 + tid;
        int m = idx >> 2, q = idx & 3;
        aoff[i] = (uint32_t)(m * A_PITCH + q * 16);
        int tok;
        if (ROUTED) { int gr = m0 + m; tok = (gr < cnt) ? g_rows_token[rowbase + gr] : 0; }
        else tok = m0 + m;
        aseg[i] = g_xh + (size_t)tok * K + q * 8;
    }
    const int bkk = tid >> 3, bslot = tid & 7;
    const uint32_t boff = (uint32_t)(bkk * BSW_PITCH + bslot * 16);
    const __half* b1s = B1 + (size_t)bkk * NCOLS + n0 + bslot * 8;
    const __half* b2s = B2 + (size_t)bkk * NCOLS + n0 + bslot * 8;

    float cg[4][2][4], cu[4][2][4];
#pragma unroll
    for (int mt = 0; mt < 4; mt++)
#pragma unroll
        for (int j = 0; j < 2; j++)
#pragma unroll
            for (int c = 0; c < 4; c++) { cg[mt][j][c] = 0.f; cu[mt][j][c] = 0.f; }

    const uint32_t a_l = (uint32_t)((wm * 64 + (lane & 15)) * A_PITCH + (lane >> 4) * 16);
    const uint32_t b_l = (uint32_t)((lane & 15) * BSW_PITCH);

    auto ISSUE = [&](int ch, int buf) {
        uint32_t s0 = sbase + buf * STG_SW;
        size_t k0 = (size_t)ch * 32;
        CPA16(s0 + aoff[0], aseg[0] + k0);
        CPA16(s0 + aoff[1], aseg[1] + k0);
        CPA16(s0 + A_BYTES + boff, b1s + k0 * NCOLS);
        CPA16(s0 + A_BYTES + BSW_BYTES + boff, b2s + k0 * NCOLS);
    };
    auto COMPUTE = [&](int buf) {
        uint32_t base = sbase + buf * STG_SW;
#pragma unroll
        for (int s = 0; s < 2; s++) {
            uint32_t a[4][4];
#pragma unroll
            for (int mt = 0; mt < 4; mt++)
                LDSM4(a[mt][0], a[mt][1], a[mt][2], a[mt][3],
                      base + a_l + mt * (16 * A_PITCH) + s * 32);
#pragma unroll
            for (int j = 0; j < 2; j++) {
                uint32_t g0, g1, u0, u1;
                uint32_t baddr = base + A_BYTES + b_l + s * (16 * BSW_PITCH) + wn * 32 + j * 16;
                LDSM2T(g0, g1, baddr);
                LDSM2T(u0, u1, baddr + BSW_BYTES);
#pragma unroll
                for (int mt = 0; mt < 4; mt++) {
                    MMA16(cg[mt][j], a[mt], g0, g1);
                    MMA16(cu[mt][j], a[mt], u0, u1);
                }
            }
        }
    };

    constexpr int NC = K / 32;
#pragma unroll
    for (int s = 0; s < NSTG - 1; s++) { ISSUE(s, s); CPCOMMIT(); }
    for (int ch = 0; ch < NC; ch++) {
        CPWAIT2();
        __syncthreads();
        int nx = ch + NSTG - 1;
        if (nx < NC) ISSUE(nx, nx % NSTG);
        CPCOMMIT();
        COMPUTE(ch % NSTG);
    }

    // ---- epilogue: silu(gate)*up -> fp16 ----
#pragma unroll
    for (int mt = 0; mt < 4; mt++) {
        int r0 = m0 + wm * 64 + mt * 16 + gid;
        size_t row0 = (size_t)(rowbase + r0);
        size_t row1 = row0 + 8;
#pragma unroll
        for (int j = 0; j < 2; j++) {
            int col = n0 + wn * 16 + j * 8 + 2 * tig;
            float g0 = cg[mt][j][0], g1 = cg[mt][j][1], g2 = cg[mt][j][2], g3 = cg[mt][j][3];
            float o0 = g0 / (1.f + expf(-g0)) * cu[mt][j][0];
            float o1 = g1 / (1.f + expf(-g1)) * cu[mt][j][1];
            float o2 = g2 / (1.f + expf(-g2)) * cu[mt][j][2];
            float o3 = g3 / (1.f + expf(-g3)) * cu[mt][j][3];
            *(uint32_t*)(C + row0 * NCOLS + col) = pk(o0, o1);
            *(uint32_t*)(C + row1 * NCOLS + col) = pk(o2, o3);
        }
    }
}

// ----------------------------- down-proj fp16 mma GEMM -----------------------
// CTA 128M x 128N. 4-stage cp.async pipeline.
template<bool ROUTED, int K>
__global__ void __launch_bounds__(256, 2) k_down_h(float* __restrict__ out)
{
    const int e = blockIdx.z;
    const int cnt = ROUTED ? g_cnt[e] : NTOK;
    const int rowbase = ROUTED ? g_off[e] : 0;
    const int m0 = blockIdx.x * 128;
    if (m0 >= cnt) return;
    const int n0 = blockIdx.y * 128;
    const __half* B = (ROUTED ? g_wdh : g_sdh) + (ROUTED ? (size_t)e * K * HDIM : 0);
    const __half* A = ROUTED ? g_hbuf : g_sbuf;

    extern __shared__ __align__(16) char sm[];
    const uint32_t sbase = smem_u32(sm);

    const int tid = threadIdx.x;
    const int lane = tid & 31, wid = tid >> 5;
    const int gid = lane >> 2, tig = lane & 3;
    const int wm = wid >> 2, wn = wid & 3;

    // ---- cp.async slots ----
    const __half* aseg[2];
    uint32_t aoff[2];
#pragma unroll
    for (int i = 0; i < 2; i++) {
        int idx = i * 256 + tid;
        int m = idx >> 2, q = idx & 3;
        aoff[i] = (uint32_t)(m * A_PITCH + q * 16);
        aseg[i] = A + (size_t)(rowbase + m0 + m) * K + q * 8;
    }
    const __half* bseg[2];
    uint32_t boff[2];
#pragma unroll
    for (int i = 0; i < 2; i++) {
        int idx = i * 256 + tid;
        int kk = idx >> 4, slot = idx & 15;
        boff[i] = (uint32_t)(kk * BDN_PITCH + slot * 16);
        bseg[i] = B + (size_t)kk * HDIM + n0 + slot * 8;
    }

    float cc[4][4][4];
#pragma unroll
    for (int mt = 0; mt < 4; mt++)
#pragma unroll
        for (int j = 0; j < 4; j++)
#pragma unroll
            for (int c = 0; c < 4; c++) cc[mt][j][c] = 0.f;

    const uint32_t a_l = (uint32_t)((wm * 64 + (lane & 15)) * A_PITCH + (lane >> 4) * 16);
    const uint32_t b_l = (uint32_t)((lane & 15) * BDN_PITCH);

    auto ISSUE = [&](int ch, int buf) {
        uint32_t s0 = sbase + buf * STG_DN;
        size_t k0 = (size_t)ch * 32;
        CPA16(s0 + aoff[0], aseg[0] + k0);
        CPA16(s0 + aoff[1], aseg[1] + k0);
        CPA16(s0 + A_BYTES + boff[0], bseg[0] + k0 * HDIM);
        CPA16(s0 + A_BYTES + boff[1], bseg[1] + k0 * HDIM);
    };
    auto COMPUTE = [&](int buf) {
        uint32_t base = sbase + buf * STG_DN;
#pragma unroll
        for (int s = 0; s < 2; s++) {
            uint32_t a[4][4];
#pragma unroll
            for (int mt = 0; mt < 4; mt++)
                LDSM4(a[mt][0], a[mt][1], a[mt][2], a[mt][3],
                      base + a_l + mt * (16 * A_PITCH) + s * 32);
#pragma unroll
            for (int j = 0; j < 4; j++) {
                uint32_t b0, b1;
                LDSM2T(b0, b1, base + A_BYTES + b_l + s * (16 * BDN_PITCH) + wn * 64 + j * 16);
#pragma unroll
                for (int mt = 0; mt < 4; mt++)
                    MMA16(cc[mt][j], a[mt], b0, b1);
            }
        }
    };

    constexpr int NC = K / 32;
#pragma unroll
    for (int s = 0; s < NSTG - 1; s++) { ISSUE(s, s); CPCOMMIT(); }
    for (int ch = 0; ch < NC; ch++) {
        CPWAIT2();
        __syncthreads();
        int nx = ch + NSTG - 1;
        if (nx < NC) ISSUE(nx, nx % NSTG);
        CPCOMMIT();
        COMPUTE(ch % NSTG);
    }

    // ---- epilogue ----
#pragma unroll
    for (int mt = 0; mt < 4; mt++) {
        int r0 = m0 + wm * 64 + mt * 16 + gid;
        if (ROUTED) {
            int gr0 = rowbase + r0, gr1 = gr0 + 8;
            int s0 = g_rows_slot[gr0], s1 = g_rows_slot[gr1];
            float w0 = g_rows_w[gr0],  w1 = g_rows_w[gr1];
#pragma unroll
            for (int j = 0; j < 4; j++) {
                int col = n0 + wn * 32 + j * 8 + 2 * tig;
                if (s0 >= 0)
                    *(float2*)(g_partial + (size_t)s0 * HDIM + col) =
                        make_float2(w0 * cc[mt][j][0], w0 * cc[mt][j][1]);
                if (s1 >= 0)
                    *(float2*)(g_partial + (size_t)s1 * HDIM + col) =
                        make_float2(w1 * cc[mt][j][2], w1 * cc[mt][j][3]);
            }
        } else {
            int r1 = r0 + 8;
#pragma unroll
            for (int j = 0; j < 4; j++) {
                int col = n0 + wn * 32 + j * 8 + 2 * tig;
                float2 p00 = *(const float2*)(g_partial + (size_t)(2 * r0) * HDIM + col);
                float2 p01 = *(const float2*)(g_partial + (size_t)(2 * r0 + 1) * HDIM + col);
                float2 p10 = *(const float2*)(g_partial + (size_t)(2 * r1) * HDIM + col);
                float2 p11 = *(const float2*)(g_partial + (size_t)(2 * r1 + 1) * HDIM + col);
                *(float2*)(out + (size_t)r0 * HDIM + col) =
                    make_float2(cc[mt][j][0] + p00.x + p01.x,
                                cc[mt][j][1] + p00.y + p01.y);
                *(float2*)(out + (size_t)r1 * HDIM + col) =
                    make_float2(cc[mt][j][2] + p10.x + p11.x,
                                cc[mt][j][3] + p10.y + p11.y);
            }
        }
    }
}

// ----------------------------- launch ----------------------------------------
extern "C" void kernel_launch(void* const* d_in, const int* in_sizes, int n_in,
                              void* d_out, int out_size)
{
    const float* x       = (const float*)d_in[0];
    const float* gate_w  = (const float*)d_in[1];
    const float* w_gate  = (const float*)d_in[2];
    const float* w_up    = (const float*)d_in[3];
    const float* w_down  = (const float*)d_in[4];
    const float* sw_gate = (const float*)d_in[5];
    const float* sw_up   = (const float*)d_in[6];
    const float* sw_down = (const float*)d_in[7];
    float* out = (float*)d_out;

    cudaFuncSetAttribute(k_swiglu_h<true, IDIM>,
                         cudaFuncAttributeMaxDynamicSharedMemorySize, SMEM_SW);
    cudaFuncSetAttribute(k_swiglu_h<false, ISH>,
                         cudaFuncAttributeMaxDynamicSharedMemorySize, SMEM_SW);
    cudaFuncSetAttribute(k_down_h<true, IDIM>,
                         cudaFuncAttributeMaxDynamicSharedMemorySize, SMEM_DN);
    cudaFuncSetAttribute(k_down_h<false, ISH>,
                         cudaFuncAttributeMaxDynamicSharedMemorySize, SMEM_DN);

    k_reset<<<(CAP + 255) / 256, 256>>>();
    k_gate<<<NTOK, 128>>>(x, gate_w);
    k_scanplace<<<1, 256>>>();

    // fp32 -> fp16 conversions (grid-stride, 8 floats/thread/step)
    {
        int n8;
        n8 = NTOK * HDIM / 8;
        k_cvt<0><<<592, 256>>>((const float4*)x, n8);
        n8 = NEXP * HDIM * IDIM / 8;
        k_cvt<1><<<1184, 256>>>((const float4*)w_gate, n8);
        k_cvt<2><<<1184, 256>>>((const float4*)w_up, n8);
        k_cvt<3><<<1184, 256>>>((const float4*)w_down, n8);
        n8 = HDIM * ISH / 8;
        k_cvt<4><<<1184, 256>>>((const float4*)sw_gate, n8);
        k_cvt<5><<<1184, 256>>>((const float4*)sw_up, n8);
        n8 = ISH * HDIM / 8;
        k_cvt<6><<<1184, 256>>>((const float4*)sw_down, n8);
    }

    {   // routed SwiGLU -> g_hbuf (fp16)
        dim3 grid(NTOK / 128, IDIM / 64, NEXP);
        k_swiglu_h<true, IDIM><<<grid, 256, SMEM_SW>>>();
    }
    {   // shared SwiGLU -> g_sbuf (fp16)
        dim3 grid(NTOK / 128, ISH / 64, 1);
        k_swiglu_h<false, ISH><<<grid, 256, SMEM_SW>>>();
    }
    {   // routed down-proj -> g_partial (weighted scatter)
        dim3 grid(NTOK / 128, HDIM / 128, NEXP);
        k_down_h<true, IDIM><<<grid, 256, SMEM_DN>>>(out);
    }
    {   // shared down-proj -> out (combine fused)
        dim3 grid(NTOK / 128, HDIM / 128, 1);
        k_down_h<false, ISH><<<grid, 256, SMEM_DN>>>(out);
    }
}

// round 7
// speedup vs baseline: 6.1278x; 1.0774x over previous
#include <cuda_runtime.h>
#include <cuda_fp16.h>
#include <math.h>
#include <stdint.h>

// Problem constants
#define NTOK 2048
#define HDIM 2048
#define IDIM 1408
#define NEXP 8
#define ISH  2816
#define TOPK 2
#define CAP  5120

// ----------------------------- scratch --------------------------------------
__device__ int   g_cnt[NEXP];
__device__ int   g_cnt2[NEXP];
__device__ int   g_off[NEXP];
__device__ int   g_rows_token[CAP];
__device__ int   g_rows_slot[CAP];
__device__ float g_rows_w[CAP];
__device__ int   g_tki[NTOK * TOPK];
__device__ float g_tkw[NTOK * TOPK];
__device__ __half g_hbuf[(size_t)CAP * IDIM];
__device__ __half g_sbuf[(size_t)NTOK * ISH];
__device__ float g_partial[(size_t)NTOK * TOPK * HDIM];

// fp16 copies of inputs (converted per call)
__device__ __half g_xh [(size_t)NTOK * HDIM];
__device__ __half g_wgh[(size_t)NEXP * HDIM * IDIM];
__device__ __half g_wuh[(size_t)NEXP * HDIM * IDIM];
__device__ __half g_wdh[(size_t)NEXP * IDIM * HDIM];
__device__ __half g_sgh[(size_t)HDIM * ISH];
__device__ __half g_suh[(size_t)HDIM * ISH];
__device__ __half g_sdh[(size_t)ISH * HDIM];

// ----------------------------- helpers --------------------------------------
__device__ __forceinline__ uint32_t smem_u32(const void* p) {
    uint32_t a;
    asm("{ .reg .u64 t; cvta.to.shared.u64 t, %1; cvt.u32.u64 %0, t; }" : "=r"(a) : "l"(p));
    return a;
}
__device__ __forceinline__ uint32_t pk(float x, float y) {
    __half2 h = __floats2half2_rn(x, y);
    return reinterpret_cast<uint32_t&>(h);
}
#define LDSM4(r0, r1, r2, r3, addr) \
    asm volatile("ldmatrix.sync.aligned.m8n8.x4.shared.b16 {%0,%1,%2,%3}, [%4];" \
        : "=r"(r0), "=r"(r1), "=r"(r2), "=r"(r3) : "r"(addr))
#define LDSM4T(r0, r1, r2, r3, addr) \
    asm volatile("ldmatrix.sync.aligned.m8n8.x4.trans.shared.b16 {%0,%1,%2,%3}, [%4];" \
        : "=r"(r0), "=r"(r1), "=r"(r2), "=r"(r3) : "r"(addr))
#define MMA16(c, a, b0, b1) \
    asm volatile("mma.sync.aligned.m16n8k16.row.col.f32.f16.f16.f32 " \
        "{%0,%1,%2,%3},{%4,%5,%6,%7},{%8,%9},{%0,%1,%2,%3};" \
        : "+f"((c)[0]), "+f"((c)[1]), "+f"((c)[2]), "+f"((c)[3]) \
        : "r"((a)[0]), "r"((a)[1]), "r"((a)[2]), "r"((a)[3]), "r"(b0), "r"(b1))
#define CPA16(dst, src) \
    asm volatile("cp.async.cg.shared.global [%0], [%1], 16;" :: "r"(dst), "l"(src))
#define CPCOMMIT() asm volatile("cp.async.commit_group;" ::: "memory")
#define CPWAIT2()  asm volatile("cp.async.wait_group 2;" ::: "memory")

// SMEM layout (bytes). A: 128 rows x 32 halves, pitch 80. B pitches padded.
#define A_PITCH   80
#define A_BYTES   10240
#define BSW_PITCH 144
#define BSW_BYTES 4608
#define BDN_PITCH 272
#define BDN_BYTES 8704
#define STG_SW    (A_BYTES + 2 * BSW_BYTES)   // 19456
#define STG_DN    (A_BYTES + BDN_BYTES)       // 18944
#define NSTG      4
#define SMEM_SW   (NSTG * STG_SW)             // 77824
#define SMEM_DN   (NSTG * STG_DN)             // 75776

// ----------------------------- fp32 -> fp16 converts -------------------------
__device__ __forceinline__ void cvt_loop(const float4* __restrict__ src,
                                         __half* __restrict__ dst, int n8) {
    int stride = gridDim.x * blockDim.x;
    for (int i = blockIdx.x * blockDim.x + threadIdx.x; i < n8; i += stride) {
        float4 v0 = src[2 * i];
        float4 v1 = src[2 * i + 1];
        uint4 o;
        o.x = pk(v0.x, v0.y); o.y = pk(v0.z, v0.w);
        o.z = pk(v1.x, v1.y); o.w = pk(v1.z, v1.w);
        *(uint4*)(dst + (size_t)i * 8) = o;
    }
}
// big routed weights: z = 0,1,2 -> w_gate, w_up, w_down
__global__ void __launch_bounds__(256) k_cvtW(
    const float4* __restrict__ wg, const float4* __restrict__ wu,
    const float4* __restrict__ wd) {
    constexpr int n8 = NEXP * HDIM * IDIM / 8;
    int z = blockIdx.z;
    const float4* src = z == 0 ? wg : z == 1 ? wu : wd;
    __half* dst = z == 0 ? g_wgh : z == 1 ? g_wuh : g_wdh;
    cvt_loop(src, dst, n8);
}
// shared weights + x: z = 0..3 -> sw_gate, sw_up, sw_down, x
__global__ void __launch_bounds__(256) k_cvtS(
    const float4* __restrict__ sg, const float4* __restrict__ su,
    const float4* __restrict__ sd, const float4* __restrict__ x) {
    int z = blockIdx.z;
    int n8 = (z == 3) ? NTOK * HDIM / 8 : HDIM * ISH / 8;
    const float4* src = z == 0 ? sg : z == 1 ? su : z == 2 ? sd : x;
    __half* dst = z == 0 ? g_sgh : z == 1 ? g_suh : z == 2 ? g_sdh : g_xh;
    cvt_loop(src, dst, n8);
}

// ----------------------------- small kernels ---------------------------------
__global__ void k_reset() {
    int i = blockIdx.x * blockDim.x + threadIdx.x;
    if (i < NEXP) { g_cnt[i] = 0; g_cnt2[i] = 0; }
    if (i < CAP)  { g_rows_token[i] = 0; g_rows_slot[i] = -1; g_rows_w[i] = 0.f; }
}

__global__ void k_gate(const float* __restrict__ x, const float* __restrict__ gw) {
    int n = blockIdx.x;
    int tid = threadIdx.x;
    const float* xr = x + (size_t)n * HDIM;
    float acc[NEXP];
#pragma unroll
    for (int e = 0; e < NEXP; e++) acc[e] = 0.f;
    for (int h = tid; h < HDIM; h += 128) {
        float xv = xr[h];
#pragma unroll
        for (int e = 0; e < NEXP; e++) acc[e] += xv * gw[e * HDIM + h];
    }
    __shared__ float s[NEXP][128];
#pragma unroll
    for (int e = 0; e < NEXP; e++) s[e][tid] = acc[e];
    __syncthreads();
    for (int st = 64; st > 0; st >>= 1) {
        if (tid < st) {
#pragma unroll
            for (int e = 0; e < NEXP; e++) s[e][tid] += s[e][tid + st];
        }
        __syncthreads();
    }
    if (tid == 0) {
        float l[NEXP];
        float m = -1e30f;
#pragma unroll
        for (int e = 0; e < NEXP; e++) { l[e] = s[e][0]; m = fmaxf(m, l[e]); }
        float d = 0.f;
#pragma unroll
        for (int e = 0; e < NEXP; e++) d += expf(l[e] - m);
        int i1 = 0;
#pragma unroll
        for (int e = 1; e < NEXP; e++) if (l[e] > l[i1]) i1 = e;
        int i2 = -1;
#pragma unroll
        for (int e = 0; e < NEXP; e++) {
            if (e == i1) continue;
            if (i2 < 0 || l[e] > l[i2]) i2 = e;
        }
        g_tki[n * 2 + 0] = i1; g_tkw[n * 2 + 0] = expf(l[i1] - m) / d;
        g_tki[n * 2 + 1] = i2; g_tkw[n * 2 + 1] = expf(l[i2] - m) / d;
        atomicAdd(&g_cnt[i1], 1);
        atomicAdd(&g_cnt[i2], 1);
    }
}

__global__ void k_scanplace() {
    int tid = threadIdx.x;
    if (tid == 0) {
        int o = 0;
        for (int e = 0; e < NEXP; e++) {
            g_off[e] = o;
            o += ((g_cnt[e] + 127) / 128) * 128;
        }
    }
    __syncthreads();
    for (int i = tid; i < NTOK * TOPK; i += blockDim.x) {
        int e = g_tki[i];
        int p = g_off[e] + atomicAdd(&g_cnt2[e], 1);
        g_rows_token[p] = i >> 1;
        g_rows_slot[p]  = i;
        g_rows_w[p]     = g_tkw[i];
    }
}

// ----------------------------- fused SwiGLU fp16 mma GEMM --------------------
// grid (16, ISH/64, NEXP+1): z<8 routed expert z (22 N-tiles), z=8 shared (44).
// CTA 128M x 64N vs two B matrices. 4-stage cp.async pipeline, k-chunk 32.
__global__ void __launch_bounds__(256, 2) k_swiglu_f()
{
    constexpr int K = HDIM;
    const int z = blockIdx.z;
    const bool routed = (z < NEXP);
    int cnt, rowbase, ncols;
    const __half *B1, *B2;
    __half* C;
    if (routed) {
        if (blockIdx.y >= IDIM / 64) return;
        cnt = g_cnt[z]; rowbase = g_off[z]; ncols = IDIM;
        B1 = g_wgh + (size_t)z * K * IDIM;
        B2 = g_wuh + (size_t)z * K * IDIM;
        C = g_hbuf;
    } else {
        cnt = NTOK; rowbase = 0; ncols = ISH;
        B1 = g_sgh; B2 = g_suh; C = g_sbuf;
    }
    const int m0 = blockIdx.x * 128;
    if (m0 >= cnt) return;
    const int n0 = blockIdx.y * 64;

    extern __shared__ __align__(16) char sm[];
    const uint32_t sbase = smem_u32(sm);

    const int tid = threadIdx.x;
    const int lane = tid & 31, wid = tid >> 5;
    const int gid = lane >> 2, tig = lane & 3;
    const int wm = wid >> 2, wn = wid & 3;

    // ---- cp.async slots: A = 2 segs/thread, B = 1 seg/thread/matrix ----
    const __half* aseg[2];
    uint32_t aoff[2];
#pragma unroll
    for (int i = 0; i < 2; i++) {
        int idx = i * 256 + tid;
        int m = idx >> 2, q = idx & 3;
        aoff[i] = (uint32_t)(m * A_PITCH + q * 16);
        int tok;
        if (routed) { int gr = m0 + m; tok = (gr < cnt) ? g_rows_token[rowbase + gr] : 0; }
        else tok = m0 + m;
        aseg[i] = g_xh + (size_t)tok * K + q * 8;
    }
    const int bkk = tid >> 3, bslot = tid & 7;
    const uint32_t boff = (uint32_t)(bkk * BSW_PITCH + bslot * 16);
    const __half* b1s = B1 + (size_t)bkk * ncols + n0 + bslot * 8;
    const __half* b2s = B2 + (size_t)bkk * ncols + n0 + bslot * 8;

    float cg[4][2][4], cu[4][2][4];
#pragma unroll
    for (int mt = 0; mt < 4; mt++)
#pragma unroll
        for (int j = 0; j < 2; j++)
#pragma unroll
            for (int c = 0; c < 4; c++) { cg[mt][j][c] = 0.f; cu[mt][j][c] = 0.f; }

    const uint32_t a_l = (uint32_t)((wm * 64 + (lane & 15)) * A_PITCH + (lane >> 4) * 16);
    // x4.trans lane map: lanes 0-15 -> k rows 0-15, lanes 16-31 -> same k, n+8
    const uint32_t b_l4 = (uint32_t)((lane & 15) * BSW_PITCH + (lane >> 4) * 16);

    auto ISSUE = [&](int ch, int buf) {
        uint32_t s0 = sbase + buf * STG_SW;
        size_t k0 = (size_t)ch * 32;
        CPA16(s0 + aoff[0], aseg[0] + k0);
        CPA16(s0 + aoff[1], aseg[1] + k0);
        CPA16(s0 + A_BYTES + boff, b1s + k0 * ncols);
        CPA16(s0 + A_BYTES + BSW_BYTES + boff, b2s + k0 * ncols);
    };
    auto COMPUTE = [&](int buf) {
        uint32_t base = sbase + buf * STG_SW;
#pragma unroll
        for (int s = 0; s < 2; s++) {
            uint32_t a[4][4];
#pragma unroll
            for (int mt = 0; mt < 4; mt++)
                LDSM4(a[mt][0], a[mt][1], a[mt][2], a[mt][3],
                      base + a_l + mt * (16 * A_PITCH) + s * 32);
            uint32_t g[4], u[4];
            uint32_t baddr = base + A_BYTES + b_l4 + s * (16 * BSW_PITCH) + wn * 32;
            LDSM4T(g[0], g[1], g[2], g[3], baddr);
            LDSM4T(u[0], u[1], u[2], u[3], baddr + BSW_BYTES);
#pragma unroll
            for (int mt = 0; mt < 4; mt++) {
                MMA16(cg[mt][0], a[mt], g[0], g[1]);
                MMA16(cu[mt][0], a[mt], u[0], u[1]);
                MMA16(cg[mt][1], a[mt], g[2], g[3]);
                MMA16(cu[mt][1], a[mt], u[2], u[3]);
            }
        }
    };

    constexpr int NC = K / 32;
#pragma unroll
    for (int s = 0; s < NSTG - 1; s++) { ISSUE(s, s); CPCOMMIT(); }
    for (int ch = 0; ch < NC; ch++) {
        CPWAIT2();
        __syncthreads();
        int nx = ch + NSTG - 1;
        if (nx < NC) ISSUE(nx, nx % NSTG);
        CPCOMMIT();
        COMPUTE(ch % NSTG);
    }

    // ---- epilogue: silu(gate)*up -> fp16 ----
#pragma unroll
    for (int mt = 0; mt < 4; mt++) {
        int r0 = m0 + wm * 64 + mt * 16 + gid;
        size_t row0 = (size_t)(rowbase + r0);
        size_t row1 = row0 + 8;
#pragma unroll
        for (int j = 0; j < 2; j++) {
            int col = n0 + wn * 16 + j * 8 + 2 * tig;
            float g0 = cg[mt][j][0], g1 = cg[mt][j][1], g2 = cg[mt][j][2], g3 = cg[mt][j][3];
            float o0 = g0 / (1.f + expf(-g0)) * cu[mt][j][0];
            float o1 = g1 / (1.f + expf(-g1)) * cu[mt][j][1];
            float o2 = g2 / (1.f + expf(-g2)) * cu[mt][j][2];
            float o3 = g3 / (1.f + expf(-g3)) * cu[mt][j][3];
            *(uint32_t*)(C + row0 * ncols + col) = pk(o0, o1);
            *(uint32_t*)(C + row1 * ncols + col) = pk(o2, o3);
        }
    }
}

// ----------------------------- down-proj fp16 mma GEMM -----------------------
// CTA 128M x 128N. 4-stage cp.async pipeline.
template<bool ROUTED, int K>
__global__ void __launch_bounds__(256, 2) k_down_h(float* __restrict__ out)
{
    const int e = blockIdx.z;
    const int cnt = ROUTED ? g_cnt[e] : NTOK;
    const int rowbase = ROUTED ? g_off[e] : 0;
    const int m0 = blockIdx.x * 128;
    if (m0 >= cnt) return;
    const int n0 = blockIdx.y * 128;
    const __half* B = (ROUTED ? g_wdh : g_sdh) + (ROUTED ? (size_t)e * K * HDIM : 0);
    const __half* A = ROUTED ? g_hbuf : g_sbuf;

    extern __shared__ __align__(16) char sm[];
    const uint32_t sbase = smem_u32(sm);

    const int tid = threadIdx.x;
    const int lane = tid & 31, wid = tid >> 5;
    const int gid = lane >> 2, tig = lane & 3;
    const int wm = wid >> 2, wn = wid & 3;

    // ---- cp.async slots ----
    const __half* aseg[2];
    uint32_t aoff[2];
#pragma unroll
    for (int i = 0; i < 2; i++) {
        int idx = i * 256 + tid;
        int m = idx >> 2, q = idx & 3;
        aoff[i] = (uint32_t)(m * A_PITCH + q * 16);
        aseg[i] = A + (size_t)(rowbase + m0 + m) * K + q * 8;
    }
    const __half* bseg[2];
    uint32_t boff[2];
#pragma unroll
    for (int i = 0; i < 2; i++) {
        int idx = i * 256 + tid;
        int kk = idx >> 4, slot = idx & 15;
        boff[i] = (uint32_t)(kk * BDN_PITCH + slot * 16);
        bseg[i] = B + (size_t)kk * HDIM + n0 + slot * 8;
    }

    float cc[4][4][4];
#pragma unroll
    for (int mt = 0; mt < 4; mt++)
#pragma unroll
        for (int j = 0; j < 4; j++)
#pragma unroll
            for (int c = 0; c < 4; c++) cc[mt][j][c] = 0.f;

    const uint32_t a_l = (uint32_t)((wm * 64 + (lane & 15)) * A_PITCH + (lane >> 4) * 16);
    const uint32_t b_l4 = (uint32_t)((lane & 15) * BDN_PITCH + (lane >> 4) * 16);

    auto ISSUE = [&](int ch, int buf) {
        uint32_t s0 = sbase + buf * STG_DN;
        size_t k0 = (size_t)ch * 32;
        CPA16(s0 + aoff[0], aseg[0] + k0);
        CPA16(s0 + aoff[1], aseg[1] + k0);
        CPA16(s0 + A_BYTES + boff[0], bseg[0] + k0 * HDIM);
        CPA16(s0 + A_BYTES + boff[1], bseg[1] + k0 * HDIM);
    };
    auto COMPUTE = [&](int buf) {
        uint32_t base = sbase + buf * STG_DN;
#pragma unroll
        for (int s = 0; s < 2; s++) {
            uint32_t a[4][4];
#pragma unroll
            for (int mt = 0; mt < 4; mt++)
                LDSM4(a[mt][0], a[mt][1], a[mt][2], a[mt][3],
                      base + a_l + mt * (16 * A_PITCH) + s * 32);
#pragma unroll
            for (int t = 0; t < 2; t++) {
                uint32_t b[4];
                LDSM4T(b[0], b[1], b[2], b[3],
                       base + A_BYTES + b_l4 + s * (16 * BDN_PITCH) + wn * 64 + t * 32);
#pragma unroll
                for (int mt = 0; mt < 4; mt++) {
                    MMA16(cc[mt][t * 2 + 0], a[mt], b[0], b[1]);
                    MMA16(cc[mt][t * 2 + 1], a[mt], b[2], b[3]);
                }
            }
        }
    };

    constexpr int NC = K / 32;
#pragma unroll
    for (int s = 0; s < NSTG - 1; s++) { ISSUE(s, s); CPCOMMIT(); }
    for (int ch = 0; ch < NC; ch++) {
        CPWAIT2();
        __syncthreads();
        int nx = ch + NSTG - 1;
        if (nx < NC) ISSUE(nx, nx % NSTG);
        CPCOMMIT();
        COMPUTE(ch % NSTG);
    }

    // ---- epilogue ----
#pragma unroll
    for (int mt = 0; mt < 4; mt++) {
        int r0 = m0 + wm * 64 + mt * 16 + gid;
        if (ROUTED) {
            int gr0 = rowbase + r0, gr1 = gr0 + 8;
            int s0 = g_rows_slot[gr0], s1 = g_rows_slot[gr1];
            float w0 = g_rows_w[gr0],  w1 = g_rows_w[gr1];
#pragma unroll
            for (int j = 0; j < 4; j++) {
                int col = n0 + wn * 32 + j * 8 + 2 * tig;
                if (s0 >= 0)
                    *(float2*)(g_partial + (size_t)s0 * HDIM + col) =
                        make_float2(w0 * cc[mt][j][0], w0 * cc[mt][j][1]);
                if (s1 >= 0)
                    *(float2*)(g_partial + (size_t)s1 * HDIM + col) =
                        make_float2(w1 * cc[mt][j][2], w1 * cc[mt][j][3]);
            }
        } else {
            int r1 = r0 + 8;
#pragma unroll
            for (int j = 0; j < 4; j++) {
                int col = n0 + wn * 32 + j * 8 + 2 * tig;
                float2 p00 = *(const float2*)(g_partial + (size_t)(2 * r0) * HDIM + col);
                float2 p01 = *(const float2*)(g_partial + (size_t)(2 * r0 + 1) * HDIM + col);
                float2 p10 = *(const float2*)(g_partial + (size_t)(2 * r1) * HDIM + col);
                float2 p11 = *(const float2*)(g_partial + (size_t)(2 * r1 + 1) * HDIM + col);
                *(float2*)(out + (size_t)r0 * HDIM + col) =
                    make_float2(cc[mt][j][0] + p00.x + p01.x,
                                cc[mt][j][1] + p00.y + p01.y);
                *(float2*)(out + (size_t)r1 * HDIM + col) =
                    make_float2(cc[mt][j][2] + p10.x + p11.x,
                                cc[mt][j][3] + p10.y + p11.y);
            }
        }
    }
}

// ----------------------------- launch ----------------------------------------
extern "C" void kernel_launch(void* const* d_in, const int* in_sizes, int n_in,
                              void* d_out, int out_size)
{
    const float* x       = (const float*)d_in[0];
    const float* gate_w  = (const float*)d_in[1];
    const float* w_gate  = (const float*)d_in[2];
    const float* w_up    = (const float*)d_in[3];
    const float* w_down  = (const float*)d_in[4];
    const float* sw_gate = (const float*)d_in[5];
    const float* sw_up   = (const float*)d_in[6];
    const float* sw_down = (const float*)d_in[7];
    float* out = (float*)d_out;

    cudaFuncSetAttribute(k_swiglu_f,
                         cudaFuncAttributeMaxDynamicSharedMemorySize, SMEM_SW);
    cudaFuncSetAttribute(k_down_h<true, IDIM>,
                         cudaFuncAttributeMaxDynamicSharedMemorySize, SMEM_DN);
    cudaFuncSetAttribute(k_down_h<false, ISH>,
                         cudaFuncAttributeMaxDynamicSharedMemorySize, SMEM_DN);

    k_reset<<<(CAP + 255) / 256, 256>>>();
    k_gate<<<NTOK, 128>>>(x, gate_w);
    k_scanplace<<<1, 256>>>();

    // fp32 -> fp16 conversions (2 launches)
    k_cvtW<<<dim3(432, 1, 3), 256>>>((const float4*)w_gate, (const float4*)w_up,
                                     (const float4*)w_down);
    k_cvtS<<<dim3(200, 1, 4), 256>>>((const float4*)sw_gate, (const float4*)sw_up,
                                     (const float4*)sw_down, (const float4*)x);

    {   // fused routed+shared SwiGLU -> g_hbuf / g_sbuf (fp16)
        dim3 grid(NTOK / 128, ISH / 64, NEXP + 1);
        k_swiglu_f<<<grid, 256, SMEM_SW>>>();
    }
    {   // routed down-proj -> g_partial (weighted scatter)
        dim3 grid(NTOK / 128, HDIM / 128, NEXP);
        k_down_h<true, IDIM><<<grid, 256, SMEM_DN>>>(out);
    }
    {   // shared down-proj -> out (combine fused)
        dim3 grid(NTOK / 128, HDIM / 128, 1);
        k_down_h<false, ISH><<<grid, 256, SMEM_DN>>>(out);
    }
}